// round 4
// baseline (speedup 1.0000x reference)
#include <cuda_runtime.h>
#include <cstdint>

// Problem constants (fixed by the dataset)
#define NNODES 50000
#define NEDGES 800000
#define FIN    512
#define HDIM   128
#define CDIM   64

// ---------------------------------------------------------------------------
// Device scratch (no allocation allowed anywhere). Kernels reference these
// directly — no cudaGetSymbolAddress in the capture path.
// ---------------------------------------------------------------------------
__device__ float g_h1  [(size_t)NNODES * HDIM];   // x@W1, reused for dropout(relu(agg1+b1))
__device__ float g_agg1[(size_t)NNODES * HDIM];
__device__ float g_h2  [(size_t)NNODES * CDIM];   // h1d@W2
__device__ float g_agg2[(size_t)NNODES * CDIM];

// ---------------------------------------------------------------------------
// Packed fp32x2 helpers (Blackwell f32x2 pipe: 2 FMAs per issue slot)
// ---------------------------------------------------------------------------
typedef unsigned long long ull;

__device__ __forceinline__ ull pack2(float lo, float hi) {
    ull r; asm("mov.b64 %0, {%1, %2};" : "=l"(r) : "f"(lo), "f"(hi)); return r;
}
__device__ __forceinline__ void unpack2(ull v, float& lo, float& hi) {
    asm("mov.b64 {%0, %1}, %2;" : "=f"(lo), "=f"(hi) : "l"(v));
}
__device__ __forceinline__ ull fma2(ull a, ull b, ull c) {
    ull d; asm("fma.rn.f32x2 %0, %1, %2, %3;" : "=l"(d) : "l"(a), "l"(b), "l"(c)); return d;
}

// Vector float atomic reduce (PTX ISA 8.1+, sm_90+): one red for 4 floats.
__device__ __forceinline__ void red_add_v4(float* addr, float a, float b, float c, float d) {
    asm volatile("red.global.add.v4.f32 [%0], {%1, %2, %3, %4};"
                 :: "l"(addr), "f"(a), "f"(b), "f"(c), "f"(d) : "memory");
}

// ---------------------------------------------------------------------------
// Zero-fill both aggregation buffers (needed on every graph replay)
// ---------------------------------------------------------------------------
__global__ __launch_bounds__(256)
void zero_aggs_kernel() {
    constexpr int N1 = NNODES * HDIM / 4;
    constexpr int N2 = NNODES * CDIM / 4;
    int i = blockIdx.x * blockDim.x + threadIdx.x;
    float4 z = make_float4(0.f, 0.f, 0.f, 0.f);
    if (i < N1) ((float4*)g_agg1)[i] = z;
    if (i < N2) ((float4*)g_agg2)[i] = z;
}

// ---------------------------------------------------------------------------
// Tiled fp32 GEMM: C[M, BN] = A[M, KTOT] @ B[KTOT, BN]
//   One block covers the full N (BN == total N: 128 or 64).
//   Accumulators packed as f32x2 pairs along M: the a-pair is a free LDS.64
//   from the K-major A tile; b is duplicated with one mov.b64 per column/k.
//   256 threads, each computes 8 rows (4 pairs) x 4 cols.
// ---------------------------------------------------------------------------
template<int BM, int BN, int BK, int KTOT>
__global__ __launch_bounds__(256)
void gemm_kernel(const float* __restrict__ A, const float* __restrict__ B,
                 float* __restrict__ C, int M) {
    constexpr int COLT = BN / 4;          // threads along N
    constexpr int ROWT = 256 / COLT;      // threads along M
    constexpr int NP   = (BM / ROWT) / 2; // row pairs per thread
    static_assert(BM / ROWT == 8, "expect TM==8");

    __shared__ __align__(16) float As[BK][BM + 2];  // K-major, +2 pad (8B-aligned, breaks conflicts)
    __shared__ __align__(16) float Bs[BK][BN];

    const int tid  = threadIdx.x;
    const int trow = tid / COLT;
    const int tcol = tid % COLT;
    const int m0   = blockIdx.x * BM;

    ull acc[NP][4];
    #pragma unroll
    for (int i = 0; i < NP; i++)
        #pragma unroll
        for (int j = 0; j < 4; j++) acc[i][j] = 0ull;  // {0.f, 0.f}

    for (int k0 = 0; k0 < KTOT; k0 += BK) {
        // --- load A tile (transposed into K-major smem) ---
        constexpr int AF4 = BM * BK / 4;
        #pragma unroll
        for (int idx = tid; idx < AF4; idx += 256) {
            int ar  = idx / (BK / 4);
            int ac4 = idx % (BK / 4);
            float4 v = make_float4(0.f, 0.f, 0.f, 0.f);
            int gr = m0 + ar;
            if (gr < M) v = *(const float4*)&A[(size_t)gr * KTOT + k0 + ac4 * 4];
            As[ac4 * 4 + 0][ar] = v.x;
            As[ac4 * 4 + 1][ar] = v.y;
            As[ac4 * 4 + 2][ar] = v.z;
            As[ac4 * 4 + 3][ar] = v.w;
        }
        // --- load B tile ---
        constexpr int BF4 = BK * BN / 4;
        #pragma unroll
        for (int idx = tid; idx < BF4; idx += 256) {
            int br  = idx / (BN / 4);
            int bc4 = idx % (BN / 4);
            *(float4*)&Bs[br][bc4 * 4] =
                *(const float4*)&B[(size_t)(k0 + br) * BN + bc4 * 4];
        }
        __syncthreads();

        #pragma unroll
        for (int kk = 0; kk < BK; kk++) {
            ull a[NP];
            #pragma unroll
            for (int i = 0; i < NP; i++)
                a[i] = *(const ull*)&As[kk][i * (2 * ROWT) + trow * 2];
            float4 b = *(const float4*)&Bs[kk][tcol * 4];
            ull b0 = pack2(b.x, b.x), b1 = pack2(b.y, b.y);
            ull b2 = pack2(b.z, b.z), b3 = pack2(b.w, b.w);
            #pragma unroll
            for (int i = 0; i < NP; i++) {
                acc[i][0] = fma2(a[i], b0, acc[i][0]);
                acc[i][1] = fma2(a[i], b1, acc[i][1]);
                acc[i][2] = fma2(a[i], b2, acc[i][2]);
                acc[i][3] = fma2(a[i], b3, acc[i][3]);
            }
        }
        __syncthreads();
    }

    // --- epilogue: coalesced float4 stores ---
    #pragma unroll
    for (int i = 0; i < NP; i++) {
        int r0 = m0 + i * (2 * ROWT) + trow * 2;
        float lo[4], hi[4];
        #pragma unroll
        for (int j = 0; j < 4; j++) unpack2(acc[i][j], lo[j], hi[j]);
        if (r0 < M)
            *(float4*)&C[(size_t)r0 * BN + tcol * 4] = make_float4(lo[0], lo[1], lo[2], lo[3]);
        if (r0 + 1 < M)
            *(float4*)&C[(size_t)(r0 + 1) * BN + tcol * 4] = make_float4(hi[0], hi[1], hi[2], hi[3]);
    }
}

// ---------------------------------------------------------------------------
// Edge scatter: agg[dst] += h[src] * ew   (NCOL/4 threads per edge)
// ---------------------------------------------------------------------------
template<int NCOL>
__global__ __launch_bounds__(256)
void scatter_kernel(const float* __restrict__ h, const int* __restrict__ src,
                    const int* __restrict__ dst, const float* __restrict__ ew,
                    float* __restrict__ agg, int E) {
    constexpr int TPE = NCOL / 4;
    int gid = blockIdx.x * blockDim.x + threadIdx.x;
    int e = gid / TPE;
    if (e >= E) return;
    int c = (gid % TPE) * 4;
    int s = src[e], d = dst[e];
    float w = ew[e];
    float4 v = *(const float4*)&h[(size_t)s * NCOL + c];
    red_add_v4(&agg[(size_t)d * NCOL + c], v.x * w, v.y * w, v.z * w, v.w * w);
}

// ---------------------------------------------------------------------------
// g_h1 = relu(g_agg1 + b1) * (mask >= 0.5 ? 2 : 0)     (H = 128, float4)
// ---------------------------------------------------------------------------
__global__ __launch_bounds__(256)
void bias_relu_drop_kernel(const float* __restrict__ b,
                           const float* __restrict__ mask, int total4) {
    int i = blockIdx.x * blockDim.x + threadIdx.x;
    if (i >= total4) return;
    int base = i * 4;
    int c = base & (HDIM - 1);
    float4 v  = *(const float4*)&g_agg1[base];
    float4 mk = *(const float4*)&mask[base];
    v.x = fmaxf(v.x + b[c + 0], 0.f) * (mk.x >= 0.5f ? 2.f : 0.f);
    v.y = fmaxf(v.y + b[c + 1], 0.f) * (mk.y >= 0.5f ? 2.f : 0.f);
    v.z = fmaxf(v.z + b[c + 2], 0.f) * (mk.z >= 0.5f ? 2.f : 0.f);
    v.w = fmaxf(v.w + b[c + 3], 0.f) * (mk.w >= 0.5f ? 2.f : 0.f);
    *(float4*)&g_h1[base] = v;
}

// ---------------------------------------------------------------------------
// out = log_softmax(g_agg2 + b)  over 64 cols; one warp per row, 2 cols/lane.
// ---------------------------------------------------------------------------
__global__ __launch_bounds__(256)
void logsoftmax_kernel(const float* __restrict__ b, float* __restrict__ out, int N) {
    int warp = (blockIdx.x * blockDim.x + threadIdx.x) >> 5;
    int lane = threadIdx.x & 31;
    if (warp >= N) return;
    const float* row = g_agg2 + (size_t)warp * CDIM;
    float2 v = *(const float2*)&row[lane * 2];
    v.x += b[lane * 2 + 0];
    v.y += b[lane * 2 + 1];
    float m = fmaxf(v.x, v.y);
    #pragma unroll
    for (int o = 16; o > 0; o >>= 1) m = fmaxf(m, __shfl_xor_sync(0xFFFFFFFFu, m, o));
    float s = expf(v.x - m) + expf(v.y - m);
    #pragma unroll
    for (int o = 16; o > 0; o >>= 1) s += __shfl_xor_sync(0xFFFFFFFFu, s, o);
    float lse = m + logf(s);
    float2 r = make_float2(v.x - lse, v.y - lse);
    *(float2*)&out[(size_t)warp * CDIM + lane * 2] = r;
}

// ---------------------------------------------------------------------------
// Launch — pure kernel launches, nothing else (max capture safety)
// ---------------------------------------------------------------------------
extern "C" void kernel_launch(void* const* d_in, const int* in_sizes, int n_in,
                              void* d_out, int out_size) {
    const float* x    = (const float*)d_in[0];   // [N, 512]
    const float* ew   = (const float*)d_in[1];   // [E]
    const float* W1   = (const float*)d_in[2];   // [512, 128]
    const float* b1   = (const float*)d_in[3];   // [128]
    const float* W2   = (const float*)d_in[4];   // [128, 64]
    const float* b2   = (const float*)d_in[5];   // [64]
    const float* mask = (const float*)d_in[6];   // [N, 128]
    const int*   ei   = (const int*)d_in[7];     // [2, E]
    float* out = (float*)d_out;

    const int N = NNODES, E = NEDGES;
    const int* src = ei;
    const int* dst = ei + E;

    // Device-global scratch pointers come from the device linker via small
    // shim: kernels that need them reference the globals directly; GEMM and
    // scatter take them as plain pointers obtained below at compile time is
    // not possible from host, so those kernels get them via template-free
    // device-global-referencing wrappers? -- simpler: GEMM/scatter accept
    // pointers; we get them once per process through a device lambda is not
    // allowed either. Instead: use the fact that taking the address is only
    // needed device-side -> wrap launches with globals passed by tiny
    // device-visible holder kernels is overkill. cudaGetSymbolAddress is
    // capture-safe (no stream op), keep it but call it only here.
    static float *h1 = nullptr, *agg1 = nullptr, *h2 = nullptr, *agg2 = nullptr;
    if (!h1) {
        cudaGetSymbolAddress((void**)&h1,   g_h1);
        cudaGetSymbolAddress((void**)&agg1, g_agg1);
        cudaGetSymbolAddress((void**)&h2,   g_h2);
        cudaGetSymbolAddress((void**)&agg2, g_agg2);
    }

    // 1) clear aggregation buffers (both in one grid)
    {
        constexpr int n4 = NNODES * HDIM / 4;
        zero_aggs_kernel<<<(n4 + 255) / 256, 256>>>();
    }

    // 2) h1 = x @ W1            [50000,512] x [512,128]
    gemm_kernel<64, HDIM, 32, FIN><<<(N + 63) / 64, 256>>>(x, W1, h1, N);

    // 3) agg1[dst] += h1[src] * ew
    {
        int total = E * (HDIM / 4);
        scatter_kernel<HDIM><<<(total + 255) / 256, 256>>>(h1, src, dst, ew, agg1, E);
    }

    // 4) h1d = relu(agg1 + b1) * dropout   (overwrites h1)
    {
        int total4 = N * HDIM / 4;
        bias_relu_drop_kernel<<<(total4 + 255) / 256, 256>>>(b1, mask, total4);
    }

    // 5) h2 = h1d @ W2           [50000,128] x [128,64]
    gemm_kernel<128, CDIM, 32, HDIM><<<(N + 127) / 128, 256>>>(h1, W2, h2, N);

    // 6) agg2[dst] += h2[src] * ew
    {
        int total = E * (CDIM / 4);
        scatter_kernel<CDIM><<<(total + 255) / 256, 256>>>(h2, src, dst, ew, agg2, E);
    }

    // 7) out = log_softmax(agg2 + b2)
    logsoftmax_kernel<<<(N * 32 + 255) / 256, 256>>>(b2, out, N);
}

// round 6
// speedup vs baseline: 1.3107x; 1.3107x over previous
#include <cuda_runtime.h>
#include <cstdint>

// Problem constants (fixed by the dataset)
#define NNODES 50000
#define NEDGES 800000
#define FIN    512
#define HDIM   128
#define CDIM   64

#define SCAN_BLK 256
#define NB_SCAN  ((NNODES + SCAN_BLK - 1) / SCAN_BLK)   // 196

// ---------------------------------------------------------------------------
// Device scratch (no allocation allowed anywhere)
// ---------------------------------------------------------------------------
__device__ float g_h1  [(size_t)NNODES * HDIM];   // x@W1 (pre-bias)
__device__ float g_agg1[(size_t)NNODES * HDIM];   // layer-1 aggregation
__device__ float g_h2  [(size_t)NNODES * CDIM];   // act(agg1)@W2
__device__ int   g_deg   [NNODES];                // per-dst degree
__device__ int   g_offs  [NNODES];                // CSR exclusive offsets
__device__ int   g_cursor[NNODES];                // bin cursors
__device__ int   g_bsum  [NB_SCAN];               // block sums for scan
__device__ int2  g_bin   [NEDGES];                // binned (src, weight-bits)

// ---------------------------------------------------------------------------
// Packed fp32x2 helpers (2 FMAs per issue slot; PTX-only form)
// ---------------------------------------------------------------------------
typedef unsigned long long ull;

__device__ __forceinline__ ull pack2(float lo, float hi) {
    ull r; asm("mov.b64 %0, {%1, %2};" : "=l"(r) : "f"(lo), "f"(hi)); return r;
}
__device__ __forceinline__ void unpack2(ull v, float& lo, float& hi) {
    asm("mov.b64 {%0, %1}, %2;" : "=f"(lo), "=f"(hi) : "l"(v));
}
__device__ __forceinline__ ull fma2(ull a, ull b, ull c) {
    ull d; asm("fma.rn.f32x2 %0, %1, %2, %3;" : "=l"(d) : "l"(a), "l"(b), "l"(c)); return d;
}

// ===========================================================================
// CSR build: zero -> histogram -> 3-phase scan -> bin
// ===========================================================================
__global__ __launch_bounds__(256)
void zero_deg_kernel() {
    int i = blockIdx.x * blockDim.x + threadIdx.x;
    if (i < NNODES) g_deg[i] = 0;
}

__global__ __launch_bounds__(256)
void hist_kernel(const int* __restrict__ dst) {
    int e = blockIdx.x * blockDim.x + threadIdx.x;
    if (e < NEDGES) atomicAdd(&g_deg[dst[e]], 1);
}

// phase 1: per-block sum of 256 degrees
__global__ __launch_bounds__(SCAN_BLK)
void scan1_kernel() {
    __shared__ int sh[SCAN_BLK];
    int i = blockIdx.x * SCAN_BLK + threadIdx.x;
    int v = (i < NNODES) ? g_deg[i] : 0;
    sh[threadIdx.x] = v;
    __syncthreads();
    #pragma unroll
    for (int s = SCAN_BLK / 2; s > 0; s >>= 1) {
        if (threadIdx.x < s) sh[threadIdx.x] += sh[threadIdx.x + s];
        __syncthreads();
    }
    if (threadIdx.x == 0) g_bsum[blockIdx.x] = sh[0];
}

// phase 2: exclusive scan of the 196 block sums (serial; trivial size)
__global__ void scan2_kernel() {
    if (threadIdx.x == 0) {
        int run = 0;
        for (int b = 0; b < NB_SCAN; b++) {
            int v = g_bsum[b];
            g_bsum[b] = run;
            run += v;
        }
    }
}

// phase 3: block-local exclusive scan + block base -> offs & cursor
__global__ __launch_bounds__(SCAN_BLK)
void scan3_kernel() {
    __shared__ int sh[SCAN_BLK];
    int i = blockIdx.x * SCAN_BLK + threadIdx.x;
    int v = (i < NNODES) ? g_deg[i] : 0;
    sh[threadIdx.x] = v;
    __syncthreads();
    // Hillis-Steele inclusive scan
    #pragma unroll
    for (int s = 1; s < SCAN_BLK; s <<= 1) {
        int add = (threadIdx.x >= s) ? sh[threadIdx.x - s] : 0;
        __syncthreads();
        sh[threadIdx.x] += add;
        __syncthreads();
    }
    if (i < NNODES) {
        int excl = sh[threadIdx.x] - v + g_bsum[blockIdx.x];
        g_offs[i]   = excl;
        g_cursor[i] = excl;
    }
}

__global__ __launch_bounds__(256)
void bin_kernel(const int* __restrict__ src, const int* __restrict__ dst,
                const float* __restrict__ ew) {
    int e = blockIdx.x * blockDim.x + threadIdx.x;
    if (e >= NEDGES) return;
    int d   = dst[e];
    int pos = atomicAdd(&g_cursor[d], 1);
    g_bin[pos] = make_int2(src[e], __float_as_int(ew[e]));
}

// ===========================================================================
// GEMM1 (SIMT f32x2): h1[50000,128] = x[50000,512] @ W1[512,128]
//   BM=64, BN=128, BK=32; 256 threads; 8 rows (4 f32x2 pairs) x 4 cols each.
// ===========================================================================
__global__ __launch_bounds__(256)
void gemm1_kernel(const float* __restrict__ A, const float* __restrict__ B, int M) {
    constexpr int BM = 64, BN = HDIM, BK = 32, KTOT = FIN;
    constexpr int COLT = BN / 4;          // 32
    constexpr int ROWT = 256 / COLT;      // 8
    constexpr int NP   = (BM / ROWT) / 2; // 4

    __shared__ __align__(16) float As[BK][BM + 2];
    __shared__ __align__(16) float Bs[BK][BN];

    const int tid  = threadIdx.x;
    const int trow = tid / COLT;
    const int tcol = tid % COLT;
    const int m0   = blockIdx.x * BM;

    ull acc[NP][4];
    #pragma unroll
    for (int i = 0; i < NP; i++)
        #pragma unroll
        for (int j = 0; j < 4; j++) acc[i][j] = 0ull;

    for (int k0 = 0; k0 < KTOT; k0 += BK) {
        #pragma unroll
        for (int idx = tid; idx < BM * BK / 4; idx += 256) {
            int ar  = idx / (BK / 4);
            int ac4 = idx % (BK / 4);
            float4 v = make_float4(0.f, 0.f, 0.f, 0.f);
            int gr = m0 + ar;
            if (gr < M) v = *(const float4*)&A[(size_t)gr * KTOT + k0 + ac4 * 4];
            As[ac4 * 4 + 0][ar] = v.x;
            As[ac4 * 4 + 1][ar] = v.y;
            As[ac4 * 4 + 2][ar] = v.z;
            As[ac4 * 4 + 3][ar] = v.w;
        }
        #pragma unroll
        for (int idx = tid; idx < BK * BN / 4; idx += 256) {
            int br  = idx / (BN / 4);
            int bc4 = idx % (BN / 4);
            *(float4*)&Bs[br][bc4 * 4] = *(const float4*)&B[(size_t)(k0 + br) * BN + bc4 * 4];
        }
        __syncthreads();

        #pragma unroll
        for (int kk = 0; kk < BK; kk++) {
            ull a[NP];
            #pragma unroll
            for (int i = 0; i < NP; i++)
                a[i] = *(const ull*)&As[kk][i * (2 * ROWT) + trow * 2];
            float4 b = *(const float4*)&Bs[kk][tcol * 4];
            ull b0 = pack2(b.x, b.x), b1 = pack2(b.y, b.y);
            ull b2 = pack2(b.z, b.z), b3 = pack2(b.w, b.w);
            #pragma unroll
            for (int i = 0; i < NP; i++) {
                acc[i][0] = fma2(a[i], b0, acc[i][0]);
                acc[i][1] = fma2(a[i], b1, acc[i][1]);
                acc[i][2] = fma2(a[i], b2, acc[i][2]);
                acc[i][3] = fma2(a[i], b3, acc[i][3]);
            }
        }
        __syncthreads();
    }

    #pragma unroll
    for (int i = 0; i < NP; i++) {
        int r0 = m0 + i * (2 * ROWT) + trow * 2;
        float lo[4], hi[4];
        #pragma unroll
        for (int j = 0; j < 4; j++) unpack2(acc[i][j], lo[j], hi[j]);
        if (r0 < M)
            *(float4*)&g_h1[(size_t)r0 * BN + tcol * 4] = make_float4(lo[0], lo[1], lo[2], lo[3]);
        if (r0 + 1 < M)
            *(float4*)&g_h1[(size_t)(r0 + 1) * BN + tcol * 4] = make_float4(hi[0], hi[1], hi[2], hi[3]);
    }
}

// ===========================================================================
// CSR aggregation, layer 1: agg1[n] = sum_{e in bin(n)} w_e * h1[src_e]
//   One warp per node; 4 cols/lane; unroll-2 over edges for MLP.
// ===========================================================================
__global__ __launch_bounds__(256)
void agg1_csr_kernel() {
    int warp = (blockIdx.x * blockDim.x + threadIdx.x) >> 5;
    int lane = threadIdx.x & 31;
    if (warp >= NNODES) return;
    int e  = g_offs[warp];
    int nd = g_deg[warp];
    int end = e + nd;

    float4 aA = make_float4(0.f, 0.f, 0.f, 0.f);
    float4 aB = make_float4(0.f, 0.f, 0.f, 0.f);
    const float* __restrict__ h = g_h1;

    for (; e + 1 < end; e += 2) {
        int2 p0 = g_bin[e], p1 = g_bin[e + 1];
        float w0 = __int_as_float(p0.y), w1 = __int_as_float(p1.y);
        float4 v0 = *(const float4*)&h[(size_t)p0.x * HDIM + lane * 4];
        float4 v1 = *(const float4*)&h[(size_t)p1.x * HDIM + lane * 4];
        aA.x = fmaf(w0, v0.x, aA.x); aA.y = fmaf(w0, v0.y, aA.y);
        aA.z = fmaf(w0, v0.z, aA.z); aA.w = fmaf(w0, v0.w, aA.w);
        aB.x = fmaf(w1, v1.x, aB.x); aB.y = fmaf(w1, v1.y, aB.y);
        aB.z = fmaf(w1, v1.z, aB.z); aB.w = fmaf(w1, v1.w, aB.w);
    }
    if (e < end) {
        int2 p0 = g_bin[e];
        float w0 = __int_as_float(p0.y);
        float4 v0 = *(const float4*)&h[(size_t)p0.x * HDIM + lane * 4];
        aA.x = fmaf(w0, v0.x, aA.x); aA.y = fmaf(w0, v0.y, aA.y);
        aA.z = fmaf(w0, v0.z, aA.z); aA.w = fmaf(w0, v0.w, aA.w);
    }
    aA.x += aB.x; aA.y += aB.y; aA.z += aB.z; aA.w += aB.w;
    *(float4*)&g_agg1[(size_t)warp * HDIM + lane * 4] = aA;
}

// ===========================================================================
// GEMM2 (SIMT f32x2) with fused activation on the A load:
//   h2 = act(agg1) @ W2 ; act(v) = relu(v + b1) * (mask >= 0.5 ? 2 : 0)
// ===========================================================================
__global__ __launch_bounds__(256)
void gemm2_fused_kernel(const float* __restrict__ b1, const float* __restrict__ mask,
                        const float* __restrict__ W2, int M) {
    constexpr int BM = 128, BN = CDIM, BK = 32, KTOT = HDIM;
    constexpr int COLT = BN / 4;          // 16
    constexpr int ROWT = 256 / COLT;      // 16
    constexpr int NP   = (BM / ROWT) / 2; // 4

    __shared__ __align__(16) float As[BK][BM + 2];
    __shared__ __align__(16) float Bs[BK][BN];

    const int tid  = threadIdx.x;
    const int trow = tid / COLT;
    const int tcol = tid % COLT;
    const int m0   = blockIdx.x * BM;

    ull acc[NP][4];
    #pragma unroll
    for (int i = 0; i < NP; i++)
        #pragma unroll
        for (int j = 0; j < 4; j++) acc[i][j] = 0ull;

    for (int k0 = 0; k0 < KTOT; k0 += BK) {
        #pragma unroll
        for (int idx = tid; idx < BM * BK / 4; idx += 256) {
            int ar  = idx / (BK / 4);
            int ac4 = idx % (BK / 4);
            float4 v = make_float4(0.f, 0.f, 0.f, 0.f);
            int gr = m0 + ar;
            if (gr < M) {
                size_t base = (size_t)gr * HDIM + k0 + ac4 * 4;
                v          = *(const float4*)&g_agg1[base];
                float4 mk  = *(const float4*)&mask[base];
                float4 bb  = *(const float4*)&b1[k0 + ac4 * 4];
                v.x = fmaxf(v.x + bb.x, 0.f) * (mk.x >= 0.5f ? 2.f : 0.f);
                v.y = fmaxf(v.y + bb.y, 0.f) * (mk.y >= 0.5f ? 2.f : 0.f);
                v.z = fmaxf(v.z + bb.z, 0.f) * (mk.z >= 0.5f ? 2.f : 0.f);
                v.w = fmaxf(v.w + bb.w, 0.f) * (mk.w >= 0.5f ? 2.f : 0.f);
            }
            As[ac4 * 4 + 0][ar] = v.x;
            As[ac4 * 4 + 1][ar] = v.y;
            As[ac4 * 4 + 2][ar] = v.z;
            As[ac4 * 4 + 3][ar] = v.w;
        }
        #pragma unroll
        for (int idx = tid; idx < BK * BN / 4; idx += 256) {
            int br  = idx / (BN / 4);
            int bc4 = idx % (BN / 4);
            *(float4*)&Bs[br][bc4 * 4] = *(const float4*)&W2[(size_t)(k0 + br) * BN + bc4 * 4];
        }
        __syncthreads();

        #pragma unroll
        for (int kk = 0; kk < BK; kk++) {
            ull a[NP];
            #pragma unroll
            for (int i = 0; i < NP; i++)
                a[i] = *(const ull*)&As[kk][i * (2 * ROWT) + trow * 2];
            float4 b = *(const float4*)&Bs[kk][tcol * 4];
            ull b0 = pack2(b.x, b.x), b1p = pack2(b.y, b.y);
            ull b2 = pack2(b.z, b.z), b3p = pack2(b.w, b.w);
            #pragma unroll
            for (int i = 0; i < NP; i++) {
                acc[i][0] = fma2(a[i], b0,  acc[i][0]);
                acc[i][1] = fma2(a[i], b1p, acc[i][1]);
                acc[i][2] = fma2(a[i], b2,  acc[i][2]);
                acc[i][3] = fma2(a[i], b3p, acc[i][3]);
            }
        }
        __syncthreads();
    }

    #pragma unroll
    for (int i = 0; i < NP; i++) {
        int r0 = m0 + i * (2 * ROWT) + trow * 2;
        float lo[4], hi[4];
        #pragma unroll
        for (int j = 0; j < 4; j++) unpack2(acc[i][j], lo[j], hi[j]);
        if (r0 < M)
            *(float4*)&g_h2[(size_t)r0 * BN + tcol * 4] = make_float4(lo[0], lo[1], lo[2], lo[3]);
        if (r0 + 1 < M)
            *(float4*)&g_h2[(size_t)(r0 + 1) * BN + tcol * 4] = make_float4(hi[0], hi[1], hi[2], hi[3]);
    }
}

// ===========================================================================
// CSR aggregation, layer 2, fused bias + log-softmax:
//   row = sum w_e * h2[src_e];  out = log_softmax(row + b2)
//   One warp per node; 2 cols/lane; unroll-2 over edges.
// ===========================================================================
__global__ __launch_bounds__(256)
void agg2_softmax_kernel(const float* __restrict__ b2, float* __restrict__ out) {
    int warp = (blockIdx.x * blockDim.x + threadIdx.x) >> 5;
    int lane = threadIdx.x & 31;
    if (warp >= NNODES) return;
    int e  = g_offs[warp];
    int nd = g_deg[warp];
    int end = e + nd;

    float2 aA = make_float2(0.f, 0.f);
    float2 aB = make_float2(0.f, 0.f);
    const float* __restrict__ h = g_h2;

    for (; e + 1 < end; e += 2) {
        int2 p0 = g_bin[e], p1 = g_bin[e + 1];
        float w0 = __int_as_float(p0.y), w1 = __int_as_float(p1.y);
        float2 v0 = *(const float2*)&h[(size_t)p0.x * CDIM + lane * 2];
        float2 v1 = *(const float2*)&h[(size_t)p1.x * CDIM + lane * 2];
        aA.x = fmaf(w0, v0.x, aA.x); aA.y = fmaf(w0, v0.y, aA.y);
        aB.x = fmaf(w1, v1.x, aB.x); aB.y = fmaf(w1, v1.y, aB.y);
    }
    if (e < end) {
        int2 p0 = g_bin[e];
        float w0 = __int_as_float(p0.y);
        float2 v0 = *(const float2*)&h[(size_t)p0.x * CDIM + lane * 2];
        aA.x = fmaf(w0, v0.x, aA.x); aA.y = fmaf(w0, v0.y, aA.y);
    }
    float2 bb = *(const float2*)&b2[lane * 2];
    float vx = aA.x + aB.x + bb.x;
    float vy = aA.y + aB.y + bb.y;

    float m = fmaxf(vx, vy);
    #pragma unroll
    for (int o = 16; o > 0; o >>= 1) m = fmaxf(m, __shfl_xor_sync(0xFFFFFFFFu, m, o));
    float s = expf(vx - m) + expf(vy - m);
    #pragma unroll
    for (int o = 16; o > 0; o >>= 1) s += __shfl_xor_sync(0xFFFFFFFFu, s, o);
    float lse = m + logf(s);
    *(float2*)&out[(size_t)warp * CDIM + lane * 2] = make_float2(vx - lse, vy - lse);
}

// ===========================================================================
// Launch — kernel launches only
// ===========================================================================
extern "C" void kernel_launch(void* const* d_in, const int* in_sizes, int n_in,
                              void* d_out, int out_size) {
    const float* x    = (const float*)d_in[0];   // [N, 512]
    const float* ew   = (const float*)d_in[1];   // [E]
    const float* W1   = (const float*)d_in[2];   // [512, 128]
    const float* b1   = (const float*)d_in[3];   // [128]
    const float* W2   = (const float*)d_in[4];   // [128, 64]
    const float* b2   = (const float*)d_in[5];   // [64]
    const float* mask = (const float*)d_in[6];   // [N, 128]
    const int*   ei   = (const int*)d_in[7];     // [2, E]
    float* out = (float*)d_out;

    const int N = NNODES, E = NEDGES;
    const int* src = ei;
    const int* dst = ei + E;

    // --- CSR build (shared by both aggregation layers) ---
    zero_deg_kernel<<<(N + 255) / 256, 256>>>();
    hist_kernel<<<(E + 255) / 256, 256>>>(dst);
    scan1_kernel<<<NB_SCAN, SCAN_BLK>>>();
    scan2_kernel<<<1, 32>>>();
    scan3_kernel<<<NB_SCAN, SCAN_BLK>>>();
    bin_kernel<<<(E + 255) / 256, 256>>>(src, dst, ew);

    // --- layer 1 ---
    gemm1_kernel<<<(N + 63) / 64, 256>>>(x, W1, N);
    agg1_csr_kernel<<<(N * 32 + 255) / 256, 256>>>();

    // --- layer 2 (activation fused into GEMM2 A-load) ---
    gemm2_fused_kernel<<<(N + 127) / 128, 256>>>(b1, mask, W2, N);
    agg2_softmax_kernel<<<(N * 32 + 255) / 256, 256>>>(b2, out);
}

// round 11
// speedup vs baseline: 1.4130x; 1.0780x over previous
#include <cuda_runtime.h>
#include <cstdint>

// Problem constants (fixed by the dataset)
#define NNODES 50000
#define NEDGES 800000
#define FIN    512
#define HDIM   128
#define CDIM   64

#define SCAN_BLK 256
#define NB_SCAN  ((NNODES + SCAN_BLK - 1) / SCAN_BLK)   // 196

// ---------------------------------------------------------------------------
// Device scratch (no allocation allowed anywhere)
// ---------------------------------------------------------------------------
__device__ float g_h1  [(size_t)NNODES * HDIM];   // x@W1 (pre-bias)
__device__ float g_agg1[(size_t)NNODES * HDIM];   // layer-1 aggregation
__device__ float g_h2  [(size_t)NNODES * CDIM];   // act(agg1)@W2
__device__ int   g_deg   [NNODES];                // per-dst degree
__device__ int   g_offs  [NNODES];                // CSR exclusive offsets
__device__ int   g_cursor[NNODES];                // bin cursors
__device__ int   g_bsum  [NB_SCAN];               // block sums for scan
__device__ int2  g_bin   [NEDGES];                // binned (src, weight-bits)

// ---------------------------------------------------------------------------
// Packed fp32x2 helpers (2 FMAs per issue slot; PTX-only form)
// ---------------------------------------------------------------------------
typedef unsigned long long ull;

__device__ __forceinline__ ull pack2(float lo, float hi) {
    ull r; asm("mov.b64 %0, {%1, %2};" : "=l"(r) : "f"(lo), "f"(hi)); return r;
}
__device__ __forceinline__ void unpack2(ull v, float& lo, float& hi) {
    asm("mov.b64 {%0, %1}, %2;" : "=f"(lo), "=f"(hi) : "l"(v));
}
__device__ __forceinline__ ull fma2(ull a, ull b, ull c) {
    ull d; asm("fma.rn.f32x2 %0, %1, %2, %3;" : "=l"(d) : "l"(a), "l"(b), "l"(c)); return d;
}

// ===========================================================================
// CSR build: zero -> histogram -> 3-phase scan -> bin
// ===========================================================================
__global__ __launch_bounds__(256)
void zero_deg_kernel() {
    int i = blockIdx.x * blockDim.x + threadIdx.x;
    if (i < NNODES) g_deg[i] = 0;
}

__global__ __launch_bounds__(256)
void hist_kernel(const int* __restrict__ dst) {
    int e = blockIdx.x * blockDim.x + threadIdx.x;
    if (e < NEDGES) atomicAdd(&g_deg[dst[e]], 1);
}

// phase 1: per-block sum of 256 degrees
__global__ __launch_bounds__(SCAN_BLK)
void scan1_kernel() {
    __shared__ int sh[SCAN_BLK];
    int i = blockIdx.x * SCAN_BLK + threadIdx.x;
    int v = (i < NNODES) ? g_deg[i] : 0;
    sh[threadIdx.x] = v;
    __syncthreads();
    #pragma unroll
    for (int s = SCAN_BLK / 2; s > 0; s >>= 1) {
        if (threadIdx.x < s) sh[threadIdx.x] += sh[threadIdx.x + s];
        __syncthreads();
    }
    if (threadIdx.x == 0) g_bsum[blockIdx.x] = sh[0];
}

// phase 2: exclusive scan of the 196 block sums — PARALLEL (1 block)
__global__ __launch_bounds__(SCAN_BLK)
void scan2_kernel() {
    __shared__ int sh[SCAN_BLK];
    int tid = threadIdx.x;
    int v = (tid < NB_SCAN) ? g_bsum[tid] : 0;
    sh[tid] = v;
    __syncthreads();
    #pragma unroll
    for (int s = 1; s < SCAN_BLK; s <<= 1) {
        int add = (tid >= s) ? sh[tid - s] : 0;
        __syncthreads();
        sh[tid] += add;
        __syncthreads();
    }
    if (tid < NB_SCAN) g_bsum[tid] = sh[tid] - v;   // exclusive
}

// phase 3: block-local exclusive scan + block base -> offs & cursor
__global__ __launch_bounds__(SCAN_BLK)
void scan3_kernel() {
    __shared__ int sh[SCAN_BLK];
    int i = blockIdx.x * SCAN_BLK + threadIdx.x;
    int v = (i < NNODES) ? g_deg[i] : 0;
    sh[threadIdx.x] = v;
    __syncthreads();
    #pragma unroll
    for (int s = 1; s < SCAN_BLK; s <<= 1) {
        int add = (threadIdx.x >= s) ? sh[threadIdx.x - s] : 0;
        __syncthreads();
        sh[threadIdx.x] += add;
        __syncthreads();
    }
    if (i < NNODES) {
        int excl = sh[threadIdx.x] - v + g_bsum[blockIdx.x];
        g_offs[i]   = excl;
        g_cursor[i] = excl;
    }
}

__global__ __launch_bounds__(256)
void bin_kernel(const int* __restrict__ src, const int* __restrict__ dst,
                const float* __restrict__ ew) {
    int e = blockIdx.x * blockDim.x + threadIdx.x;
    if (e >= NEDGES) return;
    int d   = dst[e];
    int pos = atomicAdd(&g_cursor[d], 1);
    g_bin[pos] = make_int2(src[e], __float_as_int(ew[e]));
}

// ===========================================================================
// GEMM1 (SIMT f32x2): h1[50000,128] = x[50000,512] @ W1[512,128]
//   BM=128, BN=128, BK=32; 256 threads; each thread 8 rows (4 pairs) x 8 cols.
//   Per k-step: 4 LDS.64 (a-pairs) + 2 LDS.128 (b) + 8 packs + 32 FFMA2.
// ===========================================================================
__global__ __launch_bounds__(256)
void gemm1_kernel(const float* __restrict__ A, const float* __restrict__ B, int M) {
    constexpr int BM = 128, BN = HDIM, BK = 32, KTOT = FIN;
    constexpr int COLT = 16;   // threads along N (8 cols each)
    // ROWT = 16 threads along M (8 rows = 4 pairs each)

    __shared__ __align__(16) float As[BK][BM + 2];   // K-major
    __shared__ __align__(16) float Bs[BK][BN];

    const int tid  = threadIdx.x;
    const int trow = tid / COLT;       // 0..15
    const int tcol = tid % COLT;       // 0..15
    const int m0   = blockIdx.x * BM;

    ull acc[4][8];
    #pragma unroll
    for (int i = 0; i < 4; i++)
        #pragma unroll
        for (int j = 0; j < 8; j++) acc[i][j] = 0ull;

    for (int k0 = 0; k0 < KTOT; k0 += BK) {
        // A tile: 128 rows x 32 K, transposed into K-major smem (1024 float4)
        #pragma unroll
        for (int t = 0; t < 4; t++) {
            int idx = tid + t * 256;
            int ar  = idx >> 3;              // / 8
            int ac4 = idx & 7;
            float4 v = make_float4(0.f, 0.f, 0.f, 0.f);
            int gr = m0 + ar;
            if (gr < M) v = *(const float4*)&A[(size_t)gr * KTOT + k0 + ac4 * 4];
            As[ac4 * 4 + 0][ar] = v.x;
            As[ac4 * 4 + 1][ar] = v.y;
            As[ac4 * 4 + 2][ar] = v.z;
            As[ac4 * 4 + 3][ar] = v.w;
        }
        // B tile: 32 rows x 128 (1024 float4)
        #pragma unroll
        for (int t = 0; t < 4; t++) {
            int idx = tid + t * 256;
            int br  = idx >> 5;              // / 32
            int bc4 = idx & 31;
            *(float4*)&Bs[br][bc4 * 4] = *(const float4*)&B[(size_t)(k0 + br) * BN + bc4 * 4];
        }
        __syncthreads();

        #pragma unroll
        for (int kk = 0; kk < BK; kk++) {
            ull a[4];
            #pragma unroll
            for (int i = 0; i < 4; i++)
                a[i] = *(const ull*)&As[kk][i * 32 + trow * 2];
            float4 bA = *(const float4*)&Bs[kk][tcol * 8];
            float4 bB = *(const float4*)&Bs[kk][tcol * 8 + 4];
            ull bd[8];
            bd[0] = pack2(bA.x, bA.x); bd[1] = pack2(bA.y, bA.y);
            bd[2] = pack2(bA.z, bA.z); bd[3] = pack2(bA.w, bA.w);
            bd[4] = pack2(bB.x, bB.x); bd[5] = pack2(bB.y, bB.y);
            bd[6] = pack2(bB.z, bB.z); bd[7] = pack2(bB.w, bB.w);
            #pragma unroll
            for (int i = 0; i < 4; i++)
                #pragma unroll
                for (int j = 0; j < 8; j++)
                    acc[i][j] = fma2(a[i], bd[j], acc[i][j]);
        }
        __syncthreads();
    }

    // epilogue: 2 float4 stores per row half
    #pragma unroll
    for (int i = 0; i < 4; i++) {
        int r0 = m0 + i * 32 + trow * 2;
        float lo[8], hi[8];
        #pragma unroll
        for (int j = 0; j < 8; j++) unpack2(acc[i][j], lo[j], hi[j]);
        if (r0 < M) {
            float* d0 = &g_h1[(size_t)r0 * BN + tcol * 8];
            *(float4*)&d0[0] = make_float4(lo[0], lo[1], lo[2], lo[3]);
            *(float4*)&d0[4] = make_float4(lo[4], lo[5], lo[6], lo[7]);
        }
        if (r0 + 1 < M) {
            float* d1 = &g_h1[(size_t)(r0 + 1) * BN + tcol * 8];
            *(float4*)&d1[0] = make_float4(hi[0], hi[1], hi[2], hi[3]);
            *(float4*)&d1[4] = make_float4(hi[4], hi[5], hi[6], hi[7]);
        }
    }
}

// ===========================================================================
// CSR aggregation, layer 1: agg1[n] = sum_{e in bin(n)} w_e * h1[src_e]
// ===========================================================================
__global__ __launch_bounds__(256)
void agg1_csr_kernel() {
    int warp = (blockIdx.x * blockDim.x + threadIdx.x) >> 5;
    int lane = threadIdx.x & 31;
    if (warp >= NNODES) return;
    int e  = g_offs[warp];
    int nd = g_deg[warp];
    int end = e + nd;

    float4 aA = make_float4(0.f, 0.f, 0.f, 0.f);
    float4 aB = make_float4(0.f, 0.f, 0.f, 0.f);
    const float* __restrict__ h = g_h1;

    for (; e + 1 < end; e += 2) {
        int2 p0 = g_bin[e], p1 = g_bin[e + 1];
        float w0 = __int_as_float(p0.y), w1 = __int_as_float(p1.y);
        float4 v0 = *(const float4*)&h[(size_t)p0.x * HDIM + lane * 4];
        float4 v1 = *(const float4*)&h[(size_t)p1.x * HDIM + lane * 4];
        aA.x = fmaf(w0, v0.x, aA.x); aA.y = fmaf(w0, v0.y, aA.y);
        aA.z = fmaf(w0, v0.z, aA.z); aA.w = fmaf(w0, v0.w, aA.w);
        aB.x = fmaf(w1, v1.x, aB.x); aB.y = fmaf(w1, v1.y, aB.y);
        aB.z = fmaf(w1, v1.z, aB.z); aB.w = fmaf(w1, v1.w, aB.w);
    }
    if (e < end) {
        int2 p0 = g_bin[e];
        float w0 = __int_as_float(p0.y);
        float4 v0 = *(const float4*)&h[(size_t)p0.x * HDIM + lane * 4];
        aA.x = fmaf(w0, v0.x, aA.x); aA.y = fmaf(w0, v0.y, aA.y);
        aA.z = fmaf(w0, v0.z, aA.z); aA.w = fmaf(w0, v0.w, aA.w);
    }
    aA.x += aB.x; aA.y += aB.y; aA.z += aB.z; aA.w += aB.w;
    *(float4*)&g_agg1[(size_t)warp * HDIM + lane * 4] = aA;
}

// ===========================================================================
// GEMM2 (SIMT f32x2) with fused activation on the A load:
//   h2 = act(agg1) @ W2 ; act(v) = relu(v + b1) * (mask >= 0.5 ? 2 : 0)
// ===========================================================================
__global__ __launch_bounds__(256)
void gemm2_fused_kernel(const float* __restrict__ b1, const float* __restrict__ mask,
                        const float* __restrict__ W2, int M) {
    constexpr int BM = 128, BN = CDIM, BK = 32, KTOT = HDIM;
    constexpr int COLT = BN / 4;          // 16
    constexpr int ROWT = 256 / COLT;      // 16
    constexpr int NP   = (BM / ROWT) / 2; // 4

    __shared__ __align__(16) float As[BK][BM + 2];
    __shared__ __align__(16) float Bs[BK][BN];

    const int tid  = threadIdx.x;
    const int trow = tid / COLT;
    const int tcol = tid % COLT;
    const int m0   = blockIdx.x * BM;

    ull acc[NP][4];
    #pragma unroll
    for (int i = 0; i < NP; i++)
        #pragma unroll
        for (int j = 0; j < 4; j++) acc[i][j] = 0ull;

    for (int k0 = 0; k0 < KTOT; k0 += BK) {
        #pragma unroll
        for (int idx = tid; idx < BM * BK / 4; idx += 256) {
            int ar  = idx / (BK / 4);
            int ac4 = idx % (BK / 4);
            float4 v = make_float4(0.f, 0.f, 0.f, 0.f);
            int gr = m0 + ar;
            if (gr < M) {
                size_t base = (size_t)gr * HDIM + k0 + ac4 * 4;
                v          = *(const float4*)&g_agg1[base];
                float4 mk  = *(const float4*)&mask[base];
                float4 bb  = *(const float4*)&b1[k0 + ac4 * 4];
                v.x = fmaxf(v.x + bb.x, 0.f) * (mk.x >= 0.5f ? 2.f : 0.f);
                v.y = fmaxf(v.y + bb.y, 0.f) * (mk.y >= 0.5f ? 2.f : 0.f);
                v.z = fmaxf(v.z + bb.z, 0.f) * (mk.z >= 0.5f ? 2.f : 0.f);
                v.w = fmaxf(v.w + bb.w, 0.f) * (mk.w >= 0.5f ? 2.f : 0.f);
            }
            As[ac4 * 4 + 0][ar] = v.x;
            As[ac4 * 4 + 1][ar] = v.y;
            As[ac4 * 4 + 2][ar] = v.z;
            As[ac4 * 4 + 3][ar] = v.w;
        }
        #pragma unroll
        for (int idx = tid; idx < BK * BN / 4; idx += 256) {
            int br  = idx / (BN / 4);
            int bc4 = idx % (BN / 4);
            *(float4*)&Bs[br][bc4 * 4] = *(const float4*)&W2[(size_t)(k0 + br) * BN + bc4 * 4];
        }
        __syncthreads();

        #pragma unroll
        for (int kk = 0; kk < BK; kk++) {
            ull a[NP];
            #pragma unroll
            for (int i = 0; i < NP; i++)
                a[i] = *(const ull*)&As[kk][i * (2 * ROWT) + trow * 2];
            float4 b = *(const float4*)&Bs[kk][tcol * 4];
            ull b0 = pack2(b.x, b.x), b1p = pack2(b.y, b.y);
            ull b2 = pack2(b.z, b.z), b3p = pack2(b.w, b.w);
            #pragma unroll
            for (int i = 0; i < NP; i++) {
                acc[i][0] = fma2(a[i], b0,  acc[i][0]);
                acc[i][1] = fma2(a[i], b1p, acc[i][1]);
                acc[i][2] = fma2(a[i], b2,  acc[i][2]);
                acc[i][3] = fma2(a[i], b3p, acc[i][3]);
            }
        }
        __syncthreads();
    }

    #pragma unroll
    for (int i = 0; i < NP; i++) {
        int r0 = m0 + i * (2 * ROWT) + trow * 2;
        float lo[4], hi[4];
        #pragma unroll
        for (int j = 0; j < 4; j++) unpack2(acc[i][j], lo[j], hi[j]);
        if (r0 < M)
            *(float4*)&g_h2[(size_t)r0 * BN + tcol * 4] = make_float4(lo[0], lo[1], lo[2], lo[3]);
        if (r0 + 1 < M)
            *(float4*)&g_h2[(size_t)(r0 + 1) * BN + tcol * 4] = make_float4(hi[0], hi[1], hi[2], hi[3]);
    }
}

// ===========================================================================
// CSR aggregation, layer 2, fused bias + log-softmax
// ===========================================================================
__global__ __launch_bounds__(256)
void agg2_softmax_kernel(const float* __restrict__ b2, float* __restrict__ out) {
    int warp = (blockIdx.x * blockDim.x + threadIdx.x) >> 5;
    int lane = threadIdx.x & 31;
    if (warp >= NNODES) return;
    int e  = g_offs[warp];
    int nd = g_deg[warp];
    int end = e + nd;

    float2 aA = make_float2(0.f, 0.f);
    float2 aB = make_float2(0.f, 0.f);
    const float* __restrict__ h = g_h2;

    for (; e + 1 < end; e += 2) {
        int2 p0 = g_bin[e], p1 = g_bin[e + 1];
        float w0 = __int_as_float(p0.y), w1 = __int_as_float(p1.y);
        float2 v0 = *(const float2*)&h[(size_t)p0.x * CDIM + lane * 2];
        float2 v1 = *(const float2*)&h[(size_t)p1.x * CDIM + lane * 2];
        aA.x = fmaf(w0, v0.x, aA.x); aA.y = fmaf(w0, v0.y, aA.y);
        aB.x = fmaf(w1, v1.x, aB.x); aB.y = fmaf(w1, v1.y, aB.y);
    }
    if (e < end) {
        int2 p0 = g_bin[e];
        float w0 = __int_as_float(p0.y);
        float2 v0 = *(const float2*)&h[(size_t)p0.x * CDIM + lane * 2];
        aA.x = fmaf(w0, v0.x, aA.x); aA.y = fmaf(w0, v0.y, aA.y);
    }
    float2 bb = *(const float2*)&b2[lane * 2];
    float vx = aA.x + aB.x + bb.x;
    float vy = aA.y + aB.y + bb.y;

    float m = fmaxf(vx, vy);
    #pragma unroll
    for (int o = 16; o > 0; o >>= 1) m = fmaxf(m, __shfl_xor_sync(0xFFFFFFFFu, m, o));
    float s = expf(vx - m) + expf(vy - m);
    #pragma unroll
    for (int o = 16; o > 0; o >>= 1) s += __shfl_xor_sync(0xFFFFFFFFu, s, o);
    float lse = m + logf(s);
    *(float2*)&out[(size_t)warp * CDIM + lane * 2] = make_float2(vx - lse, vy - lse);
}

// ===========================================================================
// Launch — CSR build forked onto a second stream, overlapping GEMM1.
// Stream/events created once on the first call (the correctness run),
// so no resource creation happens during graph capture.
// ===========================================================================
extern "C" void kernel_launch(void* const* d_in, const int* in_sizes, int n_in,
                              void* d_out, int out_size) {
    const float* x    = (const float*)d_in[0];   // [N, 512]
    const float* ew   = (const float*)d_in[1];   // [E]
    const float* W1   = (const float*)d_in[2];   // [512, 128]
    const float* b1   = (const float*)d_in[3];   // [128]
    const float* W2   = (const float*)d_in[4];   // [128, 64]
    const float* b2   = (const float*)d_in[5];   // [64]
    const float* mask = (const float*)d_in[6];   // [N, 128]
    const int*   ei   = (const int*)d_in[7];     // [2, E]
    float* out = (float*)d_out;

    const int N = NNODES, E = NEDGES;
    const int* src = ei;
    const int* dst = ei + E;

    static cudaStream_t s2 = nullptr;
    static cudaEvent_t  evFork = nullptr, evJoin = nullptr;
    if (!s2) {
        cudaStreamCreateWithFlags(&s2, cudaStreamNonBlocking);
        cudaEventCreateWithFlags(&evFork, cudaEventDisableTiming);
        cudaEventCreateWithFlags(&evJoin, cudaEventDisableTiming);
    }

    // --- fork: CSR build on s2, concurrent with GEMM1 on the main stream ---
    cudaEventRecord(evFork, 0);
    cudaStreamWaitEvent(s2, evFork, 0);

    zero_deg_kernel<<<(N + 255) / 256, 256, 0, s2>>>();
    hist_kernel<<<(E + 255) / 256, 256, 0, s2>>>(dst);
    scan1_kernel<<<NB_SCAN, SCAN_BLK, 0, s2>>>();
    scan2_kernel<<<1, SCAN_BLK, 0, s2>>>();
    scan3_kernel<<<NB_SCAN, SCAN_BLK, 0, s2>>>();
    bin_kernel<<<(E + 255) / 256, 256, 0, s2>>>(src, dst, ew);
    cudaEventRecord(evJoin, s2);

    // --- main stream: layer-1 GEMM (independent of CSR) ---
    gemm1_kernel<<<(N + 127) / 128, 256>>>(x, W1, N);

    // --- join: aggregation needs both h1 and the CSR bins ---
    cudaStreamWaitEvent(0, evJoin, 0);
    agg1_csr_kernel<<<(N * 32 + 255) / 256, 256>>>();

    // --- layer 2 ---
    gemm2_fused_kernel<<<(N + 127) / 128, 256>>>(b1, mask, W2, N);
    agg2_softmax_kernel<<<(N * 32 + 255) / 256, 256>>>(b2, out);
}

// round 12
// speedup vs baseline: 2.0510x; 1.4516x over previous
#include <cuda_runtime.h>
#include <cuda_bf16.h>
#include <cstdint>

// Problem constants (fixed by the dataset)
#define NNODES 50000
#define NEDGES 800000
#define FIN    512
#define HDIM   128
#define CDIM   64

#define SCAN_BLK 256
#define NB_SCAN  ((NNODES + SCAN_BLK - 1) / SCAN_BLK)   // 196

// ---------------------------------------------------------------------------
// Device scratch (no allocation allowed anywhere)
// ---------------------------------------------------------------------------
__device__ float g_h1  [(size_t)NNODES * HDIM];   // x@W1 (pre-bias)
__device__ float g_agg1[(size_t)NNODES * HDIM];   // layer-1 aggregation
__device__ float g_h2  [(size_t)NNODES * CDIM];   // act(agg1)@W2
__device__ int   g_deg   [NNODES];
__device__ int   g_offs  [NNODES];
__device__ int   g_cursor[NNODES];
__device__ int   g_bsum  [NB_SCAN];
__device__ int2  g_bin   [NEDGES];
__device__ __nv_bfloat16 g_w1t_hi[HDIM * FIN];    // W1^T split-hi  [n=128][k=512]
__device__ __nv_bfloat16 g_w1t_lo[HDIM * FIN];    // W1^T split-lo

// ---------------------------------------------------------------------------
// Packed fp32x2 helpers (for the SIMT gemm2)
// ---------------------------------------------------------------------------
typedef unsigned long long ull;

__device__ __forceinline__ ull pack2(float lo, float hi) {
    ull r; asm("mov.b64 %0, {%1, %2};" : "=l"(r) : "f"(lo), "f"(hi)); return r;
}
__device__ __forceinline__ void unpack2(ull v, float& lo, float& hi) {
    asm("mov.b64 {%0, %1}, %2;" : "=f"(lo), "=f"(hi) : "l"(v));
}
__device__ __forceinline__ ull fma2(ull a, ull b, ull c) {
    ull d; asm("fma.rn.f32x2 %0, %1, %2, %3;" : "=l"(d) : "l"(a), "l"(b), "l"(c)); return d;
}

// ---------------------------------------------------------------------------
// HMMA helpers (legacy warp-level tensor core path; sm_80+ baseline PTX)
// ---------------------------------------------------------------------------
__device__ __forceinline__ uint32_t smem_u32(const void* p) {
    uint32_t a;
    asm("{ .reg .u64 t; cvta.to.shared.u64 t, %1; cvt.u32.u64 %0, t; }" : "=r"(a) : "l"(p));
    return a;
}
__device__ __forceinline__ void ldsm_x4(uint32_t* r, uint32_t addr) {
    asm volatile("ldmatrix.sync.aligned.m8n8.x4.shared.b16 {%0,%1,%2,%3}, [%4];"
                 : "=r"(r[0]), "=r"(r[1]), "=r"(r[2]), "=r"(r[3]) : "r"(addr));
}
__device__ __forceinline__ void mma_bf16(float* c, const uint32_t* a, const uint32_t* b) {
    asm volatile(
        "mma.sync.aligned.m16n8k16.row.col.f32.bf16.bf16.f32 "
        "{%0,%1,%2,%3}, {%4,%5,%6,%7}, {%8,%9}, {%0,%1,%2,%3};"
        : "+f"(c[0]), "+f"(c[1]), "+f"(c[2]), "+f"(c[3])
        : "r"(a[0]), "r"(a[1]), "r"(a[2]), "r"(a[3]), "r"(b[0]), "r"(b[1]));
}
#define CP_ASYNC16(dst, src) \
    asm volatile("cp.async.cg.shared.global [%0], [%1], 16;" :: "r"(dst), "l"(src))
#define CP_COMMIT()  asm volatile("cp.async.commit_group;" ::: "memory")
#define CP_WAIT0()   asm volatile("cp.async.wait_group 0;" ::: "memory")

// fp32 -> (hi, lo) bf16 split; returns packed hi word, writes packed lo word.
__device__ __forceinline__ uint32_t split_pair(float a, float b, uint32_t& low) {
    __nv_bfloat16 ha = __float2bfloat16(a), hb = __float2bfloat16(b);
    __nv_bfloat16 la = __float2bfloat16(a - __bfloat162float(ha));
    __nv_bfloat16 lb = __float2bfloat16(b - __bfloat162float(hb));
    low = (uint32_t)__bfloat16_as_ushort(la) | ((uint32_t)__bfloat16_as_ushort(lb) << 16);
    return (uint32_t)__bfloat16_as_ushort(ha) | ((uint32_t)__bfloat16_as_ushort(hb) << 16);
}

// ===========================================================================
// W1 prep: transpose + bf16 split.  W1[k][n] -> w1t_{hi,lo}[n][k]
// ===========================================================================
__global__ __launch_bounds__(256)
void w1prep_kernel(const float* __restrict__ W1) {
    int i = blockIdx.x * blockDim.x + threadIdx.x;
    if (i >= HDIM * FIN) return;
    int n = i & (HDIM - 1), k = i >> 7;
    float v = W1[k * HDIM + n];
    __nv_bfloat16 h = __float2bfloat16(v);
    g_w1t_hi[n * FIN + k] = h;
    g_w1t_lo[n * FIN + k] = __float2bfloat16(v - __bfloat162float(h));
}

// ===========================================================================
// CSR build: zero -> histogram -> 3-phase scan -> bin   (forked stream)
// ===========================================================================
__global__ __launch_bounds__(256)
void zero_deg_kernel() {
    int i = blockIdx.x * blockDim.x + threadIdx.x;
    if (i < NNODES) g_deg[i] = 0;
}

__global__ __launch_bounds__(256)
void hist_kernel(const int* __restrict__ dst) {
    int e = blockIdx.x * blockDim.x + threadIdx.x;
    if (e < NEDGES) atomicAdd(&g_deg[dst[e]], 1);
}

__global__ __launch_bounds__(SCAN_BLK)
void scan1_kernel() {
    __shared__ int sh[SCAN_BLK];
    int i = blockIdx.x * SCAN_BLK + threadIdx.x;
    int v = (i < NNODES) ? g_deg[i] : 0;
    sh[threadIdx.x] = v;
    __syncthreads();
    #pragma unroll
    for (int s = SCAN_BLK / 2; s > 0; s >>= 1) {
        if (threadIdx.x < s) sh[threadIdx.x] += sh[threadIdx.x + s];
        __syncthreads();
    }
    if (threadIdx.x == 0) g_bsum[blockIdx.x] = sh[0];
}

__global__ __launch_bounds__(SCAN_BLK)
void scan2_kernel() {
    __shared__ int sh[SCAN_BLK];
    int tid = threadIdx.x;
    int v = (tid < NB_SCAN) ? g_bsum[tid] : 0;
    sh[tid] = v;
    __syncthreads();
    #pragma unroll
    for (int s = 1; s < SCAN_BLK; s <<= 1) {
        int add = (tid >= s) ? sh[tid - s] : 0;
        __syncthreads();
        sh[tid] += add;
        __syncthreads();
    }
    if (tid < NB_SCAN) g_bsum[tid] = sh[tid] - v;
}

__global__ __launch_bounds__(SCAN_BLK)
void scan3_kernel() {
    __shared__ int sh[SCAN_BLK];
    int i = blockIdx.x * SCAN_BLK + threadIdx.x;
    int v = (i < NNODES) ? g_deg[i] : 0;
    sh[threadIdx.x] = v;
    __syncthreads();
    #pragma unroll
    for (int s = 1; s < SCAN_BLK; s <<= 1) {
        int add = (threadIdx.x >= s) ? sh[threadIdx.x - s] : 0;
        __syncthreads();
        sh[threadIdx.x] += add;
        __syncthreads();
    }
    if (i < NNODES) {
        int excl = sh[threadIdx.x] - v + g_bsum[blockIdx.x];
        g_offs[i]   = excl;
        g_cursor[i] = excl;
    }
}

__global__ __launch_bounds__(256)
void bin_kernel(const int* __restrict__ src, const int* __restrict__ dst,
                const float* __restrict__ ew) {
    int e = blockIdx.x * blockDim.x + threadIdx.x;
    if (e >= NEDGES) return;
    int d   = dst[e];
    int pos = atomicAdd(&g_cursor[d], 1);
    g_bin[pos] = make_int2(src[e], __float_as_int(ew[e]));
}

// ===========================================================================
// GEMM1 via legacy HMMA (mma.sync m16n8k16 bf16, fp32 acc), 3-split emu:
//   h1 = x @ W1 = Ahi*Bhi + Ahi*Blo + Alo*Bhi  (lo*lo dropped, ~2^-17/term)
// CTA: 64(M) x 128(N); 8 warps in 2x4; warp tile 32x32 (2x4 atoms).
// K chunked by 32 (2 mma k-steps), double-buffered smem:
//   A planes split in-loader from fp32; B planes cp.async from g_w1t_{hi,lo}.
// smem rows padded to 40 bf16 (80 B) -> conflict-free ldmatrix phases.
// ===========================================================================
#define G1_BM    64
#define G1_BK    32
#define G1_LDB   40                       // padded row, elements
#define G1_APL   (G1_BM * G1_LDB * 2)     // 5120 B per A plane
#define G1_BPL   (HDIM * G1_LDB * 2)      // 10240 B per B plane
#define G1_STG   (2 * G1_APL + 2 * G1_BPL) // 30720 B per stage
#define G1_SMEM  (2 * G1_STG)             // 61440 B
#define G1_NCH   (FIN / G1_BK)            // 16

// stage offsets
#define OFF_AH 0
#define OFF_AL G1_APL
#define OFF_BH (2 * G1_APL)
#define OFF_BL (2 * G1_APL + G1_BPL)

__global__ __launch_bounds__(256)
void gemm1_hmma_kernel(const float* __restrict__ A, int M) {
    extern __shared__ char smem[];
    const uint32_t sb = smem_u32(smem);
    const int tid  = threadIdx.x;
    const int wid  = tid >> 5;
    const int lane = tid & 31;
    const int wm   = wid >> 2;            // 0..1  (M)
    const int wn   = wid & 3;             // 0..3  (N)
    const int m0   = blockIdx.x * G1_BM;

    const __nv_bfloat16* __restrict__ bhp = g_w1t_hi;
    const __nv_bfloat16* __restrict__ blp = g_w1t_lo;

    float acc[2][4][4];                   // [m-atom][n-atom][frag]
    #pragma unroll
    for (int i = 0; i < 2; i++)
        #pragma unroll
        for (int j = 0; j < 4; j++)
            #pragma unroll
            for (int q = 0; q < 4; q++) acc[i][j][q] = 0.f;

    // ---- loaders -----------------------------------------------------------
    auto ldgA = [&](int k0, float4* ar) {
        #pragma unroll
        for (int p = 0; p < 2; p++) {
            int idx = tid + p * 256;      // 512 float4
            int r   = idx >> 3;
            int c4  = idx & 7;
            float4 v = make_float4(0.f, 0.f, 0.f, 0.f);
            if (m0 + r < M) v = *(const float4*)&A[(size_t)(m0 + r) * FIN + k0 + c4 * 4];
            ar[p] = v;
        }
    };
    auto stsA = [&](uint32_t stg, const float4* ar) {
        #pragma unroll
        for (int p = 0; p < 2; p++) {
            int idx = tid + p * 256;
            int r   = idx >> 3;
            int c4  = idx & 7;
            uint32_t lo0, lo1;
            uint32_t hi0 = split_pair(ar[p].x, ar[p].y, lo0);
            uint32_t hi1 = split_pair(ar[p].z, ar[p].w, lo1);
            uint32_t off = (uint32_t)(r * (G1_LDB * 2) + c4 * 8);
            *(uint2*)(smem + (stg - sb) + OFF_AH + off) = make_uint2(hi0, hi1);
            *(uint2*)(smem + (stg - sb) + OFF_AL + off) = make_uint2(lo0, lo1);
        }
    };
    auto cpB = [&](int k0, uint32_t stg) {
        #pragma unroll
        for (int p = 0; p < 4; p++) {
            int idx = tid + p * 256;      // 1024 x 16B
            int pl  = idx >> 9;           // 0 = hi, 1 = lo
            int r   = (idx & 511) >> 2;   // n-row 0..127
            int sg  = idx & 3;            // 16B segment
            const __nv_bfloat16* src =
                (pl ? blp : bhp) + (size_t)r * FIN + k0 + sg * 8;
            uint32_t dst = stg + (pl ? OFF_BL : OFF_BH)
                         + (uint32_t)(r * (G1_LDB * 2) + sg * 16);
            CP_ASYNC16(dst, src);
        }
        CP_COMMIT();
    };

    // ---- prologue: chunk 0 -------------------------------------------------
    float4 ar[2];
    ldgA(0, ar);
    cpB(0, sb);
    stsA(sb, ar);
    CP_WAIT0();
    __syncthreads();

    // per-lane ldmatrix address pieces
    const int arow = (lane & 15);
    const int acol8 = (lane >> 4) * 8;
    const int bg   = lane >> 3;
    const int brow = ((bg >> 1) * 8) + (lane & 7);
    const int bcol8 = (bg & 1) * 8;

    for (int c = 0; c < G1_NCH; c++) {
        const uint32_t cur = sb + (uint32_t)((c & 1) * G1_STG);
        const uint32_t nxt = sb + (uint32_t)(((c + 1) & 1) * G1_STG);

        if (c + 1 < G1_NCH) {             // issue next-chunk loads early
            ldgA((c + 1) * G1_BK, ar);
            cpB((c + 1) * G1_BK, nxt);
        }

        // ---- compute chunk c ----
        #pragma unroll
        for (int kk = 0; kk < G1_BK; kk += 16) {
            uint32_t afh[2][4], afl[2][4];
            #pragma unroll
            for (int am = 0; am < 2; am++) {
                uint32_t aoff = (uint32_t)((wm * 32 + am * 16 + arow) * (G1_LDB * 2)
                                           + (kk + acol8) * 2);
                ldsm_x4(afh[am], cur + OFF_AH + aoff);
                ldsm_x4(afl[am], cur + OFF_AL + aoff);
            }
            #pragma unroll
            for (int bp = 0; bp < 2; bp++) {          // n-atom pairs (0,1), (2,3)
                uint32_t boff = (uint32_t)((wn * 32 + bp * 16 + brow) * (G1_LDB * 2)
                                           + (kk + bcol8) * 2);
                uint32_t bfh[4], bfl[4];
                ldsm_x4(bfh, cur + OFF_BH + boff);
                ldsm_x4(bfl, cur + OFF_BL + boff);
                #pragma unroll
                for (int am = 0; am < 2; am++) {
                    #pragma unroll
                    for (int j = 0; j < 2; j++) {
                        float* cc = acc[am][bp * 2 + j];
                        mma_bf16(cc, afh[am], bfh + 2 * j);   // hi*hi
                        mma_bf16(cc, afh[am], bfl + 2 * j);   // hi*lo
                        mma_bf16(cc, afl[am], bfh + 2 * j);   // lo*hi
                    }
                }
            }
        }

        if (c + 1 < G1_NCH) {
            stsA(nxt, ar);
            CP_WAIT0();
        }
        __syncthreads();
    }

    // ---- epilogue: fp32 stores ---------------------------------------------
    const int erow = lane >> 2;
    const int ecol = (lane & 3) * 2;
    #pragma unroll
    for (int am = 0; am < 2; am++) {
        int r0 = m0 + wm * 32 + am * 16 + erow;
        #pragma unroll
        for (int an = 0; an < 4; an++) {
            int colb = wn * 32 + an * 8 + ecol;
            if (r0 < M)
                *(float2*)&g_h1[(size_t)r0 * HDIM + colb] =
                    make_float2(acc[am][an][0], acc[am][an][1]);
            if (r0 + 8 < M)
                *(float2*)&g_h1[(size_t)(r0 + 8) * HDIM + colb] =
                    make_float2(acc[am][an][2], acc[am][an][3]);
        }
    }
}

// ===========================================================================
// CSR aggregation, layer 1
// ===========================================================================
__global__ __launch_bounds__(256)
void agg1_csr_kernel() {
    int warp = (blockIdx.x * blockDim.x + threadIdx.x) >> 5;
    int lane = threadIdx.x & 31;
    if (warp >= NNODES) return;
    int e  = g_offs[warp];
    int nd = g_deg[warp];
    int end = e + nd;

    float4 aA = make_float4(0.f, 0.f, 0.f, 0.f);
    float4 aB = make_float4(0.f, 0.f, 0.f, 0.f);
    const float* __restrict__ h = g_h1;

    for (; e + 1 < end; e += 2) {
        int2 p0 = g_bin[e], p1 = g_bin[e + 1];
        float w0 = __int_as_float(p0.y), w1 = __int_as_float(p1.y);
        float4 v0 = *(const float4*)&h[(size_t)p0.x * HDIM + lane * 4];
        float4 v1 = *(const float4*)&h[(size_t)p1.x * HDIM + lane * 4];
        aA.x = fmaf(w0, v0.x, aA.x); aA.y = fmaf(w0, v0.y, aA.y);
        aA.z = fmaf(w0, v0.z, aA.z); aA.w = fmaf(w0, v0.w, aA.w);
        aB.x = fmaf(w1, v1.x, aB.x); aB.y = fmaf(w1, v1.y, aB.y);
        aB.z = fmaf(w1, v1.z, aB.z); aB.w = fmaf(w1, v1.w, aB.w);
    }
    if (e < end) {
        int2 p0 = g_bin[e];
        float w0 = __int_as_float(p0.y);
        float4 v0 = *(const float4*)&h[(size_t)p0.x * HDIM + lane * 4];
        aA.x = fmaf(w0, v0.x, aA.x); aA.y = fmaf(w0, v0.y, aA.y);
        aA.z = fmaf(w0, v0.z, aA.z); aA.w = fmaf(w0, v0.w, aA.w);
    }
    aA.x += aB.x; aA.y += aB.y; aA.z += aB.z; aA.w += aB.w;
    *(float4*)&g_agg1[(size_t)warp * HDIM + lane * 4] = aA;
}

// ===========================================================================
// GEMM2 (SIMT f32x2) with fused activation on the A load
// ===========================================================================
__global__ __launch_bounds__(256)
void gemm2_fused_kernel(const float* __restrict__ b1, const float* __restrict__ mask,
                        const float* __restrict__ W2, int M) {
    constexpr int BM = 128, BN = CDIM, BK = 32, KTOT = HDIM;
    constexpr int COLT = BN / 4;
    constexpr int ROWT = 256 / COLT;
    constexpr int NP   = (BM / ROWT) / 2;

    __shared__ __align__(16) float As[BK][BM + 2];
    __shared__ __align__(16) float Bs[BK][BN];

    const int tid  = threadIdx.x;
    const int trow = tid / COLT;
    const int tcol = tid % COLT;
    const int m0   = blockIdx.x * BM;

    ull acc[NP][4];
    #pragma unroll
    for (int i = 0; i < NP; i++)
        #pragma unroll
        for (int j = 0; j < 4; j++) acc[i][j] = 0ull;

    for (int k0 = 0; k0 < KTOT; k0 += BK) {
        #pragma unroll
        for (int idx = tid; idx < BM * BK / 4; idx += 256) {
            int ar  = idx / (BK / 4);
            int ac4 = idx % (BK / 4);
            float4 v = make_float4(0.f, 0.f, 0.f, 0.f);
            int gr = m0 + ar;
            if (gr < M) {
                size_t base = (size_t)gr * HDIM + k0 + ac4 * 4;
                v          = *(const float4*)&g_agg1[base];
                float4 mk  = *(const float4*)&mask[base];
                float4 bb  = *(const float4*)&b1[k0 + ac4 * 4];
                v.x = fmaxf(v.x + bb.x, 0.f) * (mk.x >= 0.5f ? 2.f : 0.f);
                v.y = fmaxf(v.y + bb.y, 0.f) * (mk.y >= 0.5f ? 2.f : 0.f);
                v.z = fmaxf(v.z + bb.z, 0.f) * (mk.z >= 0.5f ? 2.f : 0.f);
                v.w = fmaxf(v.w + bb.w, 0.f) * (mk.w >= 0.5f ? 2.f : 0.f);
            }
            As[ac4 * 4 + 0][ar] = v.x;
            As[ac4 * 4 + 1][ar] = v.y;
            As[ac4 * 4 + 2][ar] = v.z;
            As[ac4 * 4 + 3][ar] = v.w;
        }
        #pragma unroll
        for (int idx = tid; idx < BK * BN / 4; idx += 256) {
            int br  = idx / (BN / 4);
            int bc4 = idx % (BN / 4);
            *(float4*)&Bs[br][bc4 * 4] = *(const float4*)&W2[(size_t)(k0 + br) * BN + bc4 * 4];
        }
        __syncthreads();

        #pragma unroll
        for (int kk = 0; kk < BK; kk++) {
            ull a[NP];
            #pragma unroll
            for (int i = 0; i < NP; i++)
                a[i] = *(const ull*)&As[kk][i * (2 * ROWT) + trow * 2];
            float4 b = *(const float4*)&Bs[kk][tcol * 4];
            ull b0 = pack2(b.x, b.x), b1p = pack2(b.y, b.y);
            ull b2 = pack2(b.z, b.z), b3p = pack2(b.w, b.w);
            #pragma unroll
            for (int i = 0; i < NP; i++) {
                acc[i][0] = fma2(a[i], b0,  acc[i][0]);
                acc[i][1] = fma2(a[i], b1p, acc[i][1]);
                acc[i][2] = fma2(a[i], b2,  acc[i][2]);
                acc[i][3] = fma2(a[i], b3p, acc[i][3]);
            }
        }
        __syncthreads();
    }

    #pragma unroll
    for (int i = 0; i < NP; i++) {
        int r0 = m0 + i * (2 * ROWT) + trow * 2;
        float lo[4], hi[4];
        #pragma unroll
        for (int j = 0; j < 4; j++) unpack2(acc[i][j], lo[j], hi[j]);
        if (r0 < M)
            *(float4*)&g_h2[(size_t)r0 * BN + tcol * 4] = make_float4(lo[0], lo[1], lo[2], lo[3]);
        if (r0 + 1 < M)
            *(float4*)&g_h2[(size_t)(r0 + 1) * BN + tcol * 4] = make_float4(hi[0], hi[1], hi[2], hi[3]);
    }
}

// ===========================================================================
// CSR aggregation, layer 2, fused bias + log-softmax
// ===========================================================================
__global__ __launch_bounds__(256)
void agg2_softmax_kernel(const float* __restrict__ b2, float* __restrict__ out) {
    int warp = (blockIdx.x * blockDim.x + threadIdx.x) >> 5;
    int lane = threadIdx.x & 31;
    if (warp >= NNODES) return;
    int e  = g_offs[warp];
    int nd = g_deg[warp];
    int end = e + nd;

    float2 aA = make_float2(0.f, 0.f);
    float2 aB = make_float2(0.f, 0.f);
    const float* __restrict__ h = g_h2;

    for (; e + 1 < end; e += 2) {
        int2 p0 = g_bin[e], p1 = g_bin[e + 1];
        float w0 = __int_as_float(p0.y), w1 = __int_as_float(p1.y);
        float2 v0 = *(const float2*)&h[(size_t)p0.x * CDIM + lane * 2];
        float2 v1 = *(const float2*)&h[(size_t)p1.x * CDIM + lane * 2];
        aA.x = fmaf(w0, v0.x, aA.x); aA.y = fmaf(w0, v0.y, aA.y);
        aB.x = fmaf(w1, v1.x, aB.x); aB.y = fmaf(w1, v1.y, aB.y);
    }
    if (e < end) {
        int2 p0 = g_bin[e];
        float w0 = __int_as_float(p0.y);
        float2 v0 = *(const float2*)&h[(size_t)p0.x * CDIM + lane * 2];
        aA.x = fmaf(w0, v0.x, aA.x); aA.y = fmaf(w0, v0.y, aA.y);
    }
    float2 bb = *(const float2*)&b2[lane * 2];
    float vx = aA.x + aB.x + bb.x;
    float vy = aA.y + aB.y + bb.y;

    float m = fmaxf(vx, vy);
    #pragma unroll
    for (int o = 16; o > 0; o >>= 1) m = fmaxf(m, __shfl_xor_sync(0xFFFFFFFFu, m, o));
    float s = expf(vx - m) + expf(vy - m);
    #pragma unroll
    for (int o = 16; o > 0; o >>= 1) s += __shfl_xor_sync(0xFFFFFFFFu, s, o);
    float lse = m + logf(s);
    *(float2*)&out[(size_t)warp * CDIM + lane * 2] = make_float2(vx - lse, vy - lse);
}

// ===========================================================================
// Launch — CSR build forked onto a second stream, overlapping w1prep + GEMM1.
// ===========================================================================
extern "C" void kernel_launch(void* const* d_in, const int* in_sizes, int n_in,
                              void* d_out, int out_size) {
    const float* x    = (const float*)d_in[0];   // [N, 512]
    const float* ew   = (const float*)d_in[1];   // [E]
    const float* W1   = (const float*)d_in[2];   // [512, 128]
    const float* b1   = (const float*)d_in[3];   // [128]
    const float* W2   = (const float*)d_in[4];   // [128, 64]
    const float* b2   = (const float*)d_in[5];   // [64]
    const float* mask = (const float*)d_in[6];   // [N, 128]
    const int*   ei   = (const int*)d_in[7];     // [2, E]
    float* out = (float*)d_out;

    const int N = NNODES, E = NEDGES;
    const int* src = ei;
    const int* dst = ei + E;

    static cudaStream_t s2 = nullptr;
    static cudaEvent_t  evFork = nullptr, evJoin = nullptr;
    if (!s2) {
        cudaStreamCreateWithFlags(&s2, cudaStreamNonBlocking);
        cudaEventCreateWithFlags(&evFork, cudaEventDisableTiming);
        cudaEventCreateWithFlags(&evJoin, cudaEventDisableTiming);
        cudaFuncSetAttribute(gemm1_hmma_kernel,
                             cudaFuncAttributeMaxDynamicSharedMemorySize, G1_SMEM);
    }

    // --- fork: CSR build on s2 ---
    cudaEventRecord(evFork, 0);
    cudaStreamWaitEvent(s2, evFork, 0);

    zero_deg_kernel<<<(N + 255) / 256, 256, 0, s2>>>();
    hist_kernel<<<(E + 255) / 256, 256, 0, s2>>>(dst);
    scan1_kernel<<<NB_SCAN, SCAN_BLK, 0, s2>>>();
    scan2_kernel<<<1, SCAN_BLK, 0, s2>>>();
    scan3_kernel<<<NB_SCAN, SCAN_BLK, 0, s2>>>();
    bin_kernel<<<(E + 255) / 256, 256, 0, s2>>>(src, dst, ew);
    cudaEventRecord(evJoin, s2);

    // --- main stream: W1 split prep, then HMMA GEMM1 ---
    w1prep_kernel<<<(HDIM * FIN + 255) / 256, 256>>>(W1);
    gemm1_hmma_kernel<<<(N + G1_BM - 1) / G1_BM, 256, G1_SMEM>>>(x, N);

    // --- join: aggregation needs both h1 and the CSR bins ---
    cudaStreamWaitEvent(0, evJoin, 0);
    agg1_csr_kernel<<<(N * 32 + 255) / 256, 256>>>();

    // --- layer 2 ---
    gemm2_fused_kernel<<<(N + 127) / 128, 256>>>(b1, mask, W2, N);
    agg2_softmax_kernel<<<(N * 32 + 255) / 256, 256>>>(b2, out);
}

// round 13
// speedup vs baseline: 2.1040x; 1.0258x over previous
#include <cuda_runtime.h>
#include <cuda_bf16.h>
#include <cstdint>

// Problem constants (fixed by the dataset)
#define NNODES 50000
#define NEDGES 800000
#define FIN    512
#define HDIM   128
#define CDIM   64

#define SCAN_BLK 256
#define NB_SCAN  ((NNODES + SCAN_BLK - 1) / SCAN_BLK)   // 196

// ---------------------------------------------------------------------------
// Device scratch (no allocation allowed anywhere)
// ---------------------------------------------------------------------------
__device__ float g_h1  [(size_t)NNODES * HDIM];   // x@W1 (pre-bias)
__device__ float g_agg1[(size_t)NNODES * HDIM];   // layer-1 aggregation
__device__ float g_h2  [(size_t)NNODES * CDIM];   // act(agg1)@W2
__device__ int   g_deg   [NNODES];
__device__ int   g_offs  [NNODES];
__device__ int   g_cursor[NNODES];
__device__ int   g_bsum  [NB_SCAN];
__device__ int2  g_bin   [NEDGES];
__device__ __nv_bfloat16 g_w1t_hi[HDIM * FIN];    // W1^T split-hi  [n=128][k=512]
__device__ __nv_bfloat16 g_w1t_lo[HDIM * FIN];    // W1^T split-lo
__device__ __nv_bfloat16 g_w2t_hi[CDIM * HDIM];   // W2^T split-hi  [n=64][k=128]
__device__ __nv_bfloat16 g_w2t_lo[CDIM * HDIM];   // W2^T split-lo

// ---------------------------------------------------------------------------
// HMMA helpers (legacy warp-level tensor core path; sm_80+ baseline PTX)
// ---------------------------------------------------------------------------
__device__ __forceinline__ uint32_t smem_u32(const void* p) {
    uint32_t a;
    asm("{ .reg .u64 t; cvta.to.shared.u64 t, %1; cvt.u32.u64 %0, t; }" : "=r"(a) : "l"(p));
    return a;
}
__device__ __forceinline__ void ldsm_x4(uint32_t* r, uint32_t addr) {
    asm volatile("ldmatrix.sync.aligned.m8n8.x4.shared.b16 {%0,%1,%2,%3}, [%4];"
                 : "=r"(r[0]), "=r"(r[1]), "=r"(r[2]), "=r"(r[3]) : "r"(addr));
}
__device__ __forceinline__ void mma_bf16(float* c, const uint32_t* a, const uint32_t* b) {
    asm volatile(
        "mma.sync.aligned.m16n8k16.row.col.f32.bf16.bf16.f32 "
        "{%0,%1,%2,%3}, {%4,%5,%6,%7}, {%8,%9}, {%0,%1,%2,%3};"
        : "+f"(c[0]), "+f"(c[1]), "+f"(c[2]), "+f"(c[3])
        : "r"(a[0]), "r"(a[1]), "r"(a[2]), "r"(a[3]), "r"(b[0]), "r"(b[1]));
}
#define CP_ASYNC16(dst, src) \
    asm volatile("cp.async.cg.shared.global [%0], [%1], 16;" :: "r"(dst), "l"(src))
#define CP_COMMIT()  asm volatile("cp.async.commit_group;" ::: "memory")
#define CP_WAIT0()   asm volatile("cp.async.wait_group 0;" ::: "memory")

// fp32 -> (hi, lo) bf16 split; returns packed hi word, writes packed lo word.
__device__ __forceinline__ uint32_t split_pair(float a, float b, uint32_t& low) {
    __nv_bfloat16 ha = __float2bfloat16(a), hb = __float2bfloat16(b);
    __nv_bfloat16 la = __float2bfloat16(a - __bfloat162float(ha));
    __nv_bfloat16 lb = __float2bfloat16(b - __bfloat162float(hb));
    low = (uint32_t)__bfloat16_as_ushort(la) | ((uint32_t)__bfloat16_as_ushort(lb) << 16);
    return (uint32_t)__bfloat16_as_ushort(ha) | ((uint32_t)__bfloat16_as_ushort(hb) << 16);
}

// ===========================================================================
// Weight prep: transpose + bf16 split
// ===========================================================================
__global__ __launch_bounds__(256)
void w1prep_kernel(const float* __restrict__ W1) {
    int i = blockIdx.x * blockDim.x + threadIdx.x;
    if (i >= HDIM * FIN) return;
    int n = i & (HDIM - 1), k = i >> 7;
    float v = W1[k * HDIM + n];
    __nv_bfloat16 h = __float2bfloat16(v);
    g_w1t_hi[n * FIN + k] = h;
    g_w1t_lo[n * FIN + k] = __float2bfloat16(v - __bfloat162float(h));
}

__global__ __launch_bounds__(256)
void w2prep_kernel(const float* __restrict__ W2) {
    int i = blockIdx.x * blockDim.x + threadIdx.x;
    if (i >= CDIM * HDIM) return;
    int n = i & (CDIM - 1), k = i >> 6;
    float v = W2[k * CDIM + n];
    __nv_bfloat16 h = __float2bfloat16(v);
    g_w2t_hi[n * HDIM + k] = h;
    g_w2t_lo[n * HDIM + k] = __float2bfloat16(v - __bfloat162float(h));
}

// ===========================================================================
// CSR build: zero -> histogram -> 3-phase scan -> bin   (forked stream)
// ===========================================================================
__global__ __launch_bounds__(256)
void zero_deg_kernel() {
    int i = blockIdx.x * blockDim.x + threadIdx.x;
    if (i < NNODES) g_deg[i] = 0;
}

__global__ __launch_bounds__(256)
void hist_kernel(const int* __restrict__ dst) {
    int e = blockIdx.x * blockDim.x + threadIdx.x;
    if (e < NEDGES) atomicAdd(&g_deg[dst[e]], 1);
}

__global__ __launch_bounds__(SCAN_BLK)
void scan1_kernel() {
    __shared__ int sh[SCAN_BLK];
    int i = blockIdx.x * SCAN_BLK + threadIdx.x;
    int v = (i < NNODES) ? g_deg[i] : 0;
    sh[threadIdx.x] = v;
    __syncthreads();
    #pragma unroll
    for (int s = SCAN_BLK / 2; s > 0; s >>= 1) {
        if (threadIdx.x < s) sh[threadIdx.x] += sh[threadIdx.x + s];
        __syncthreads();
    }
    if (threadIdx.x == 0) g_bsum[blockIdx.x] = sh[0];
}

__global__ __launch_bounds__(SCAN_BLK)
void scan2_kernel() {
    __shared__ int sh[SCAN_BLK];
    int tid = threadIdx.x;
    int v = (tid < NB_SCAN) ? g_bsum[tid] : 0;
    sh[tid] = v;
    __syncthreads();
    #pragma unroll
    for (int s = 1; s < SCAN_BLK; s <<= 1) {
        int add = (tid >= s) ? sh[tid - s] : 0;
        __syncthreads();
        sh[tid] += add;
        __syncthreads();
    }
    if (tid < NB_SCAN) g_bsum[tid] = sh[tid] - v;
}

__global__ __launch_bounds__(SCAN_BLK)
void scan3_kernel() {
    __shared__ int sh[SCAN_BLK];
    int i = blockIdx.x * SCAN_BLK + threadIdx.x;
    int v = (i < NNODES) ? g_deg[i] : 0;
    sh[threadIdx.x] = v;
    __syncthreads();
    #pragma unroll
    for (int s = 1; s < SCAN_BLK; s <<= 1) {
        int add = (threadIdx.x >= s) ? sh[threadIdx.x - s] : 0;
        __syncthreads();
        sh[threadIdx.x] += add;
        __syncthreads();
    }
    if (i < NNODES) {
        int excl = sh[threadIdx.x] - v + g_bsum[blockIdx.x];
        g_offs[i]   = excl;
        g_cursor[i] = excl;
    }
}

__global__ __launch_bounds__(256)
void bin_kernel(const int* __restrict__ src, const int* __restrict__ dst,
                const float* __restrict__ ew) {
    int e = blockIdx.x * blockDim.x + threadIdx.x;
    if (e >= NEDGES) return;
    int d   = dst[e];
    int pos = atomicAdd(&g_cursor[d], 1);
    g_bin[pos] = make_int2(src[e], __float_as_int(ew[e]));
}

// ===========================================================================
// GEMM1 via legacy HMMA, 3-split emu: h1 = x @ W1
// CTA: 64(M) x 128(N); 8 warps 2x4; warp tile 32x32; BK=32 double-buffered.
// smem rows padded to 40 bf16 (80 B) -> conflict-free ldmatrix phases.
// ===========================================================================
#define G1_BM    64
#define G1_BK    32
#define G1_LDB   40
#define G1_APL   (G1_BM * G1_LDB * 2)      // 5120 B per A plane
#define G1_BPL   (HDIM * G1_LDB * 2)       // 10240 B per B plane
#define G1_STG   (2 * G1_APL + 2 * G1_BPL) // 30720 B per stage
#define G1_SMEM  (2 * G1_STG)              // 61440 B
#define G1_NCH   (FIN / G1_BK)             // 16

#define OFF_AH 0
#define OFF_AL G1_APL
#define OFF_BH (2 * G1_APL)
#define OFF_BL (2 * G1_APL + G1_BPL)

__global__ __launch_bounds__(256)
void gemm1_hmma_kernel(const float* __restrict__ A, int M) {
    extern __shared__ char smem[];
    const uint32_t sb = smem_u32(smem);
    const int tid  = threadIdx.x;
    const int wid  = tid >> 5;
    const int lane = tid & 31;
    const int wm   = wid >> 2;
    const int wn   = wid & 3;
    const int m0   = blockIdx.x * G1_BM;

    const __nv_bfloat16* __restrict__ bhp = g_w1t_hi;
    const __nv_bfloat16* __restrict__ blp = g_w1t_lo;

    float acc[2][4][4];
    #pragma unroll
    for (int i = 0; i < 2; i++)
        #pragma unroll
        for (int j = 0; j < 4; j++)
            #pragma unroll
            for (int q = 0; q < 4; q++) acc[i][j][q] = 0.f;

    auto ldgA = [&](int k0, float4* ar) {
        #pragma unroll
        for (int p = 0; p < 2; p++) {
            int idx = tid + p * 256;
            int r   = idx >> 3;
            int c4  = idx & 7;
            float4 v = make_float4(0.f, 0.f, 0.f, 0.f);
            if (m0 + r < M) v = *(const float4*)&A[(size_t)(m0 + r) * FIN + k0 + c4 * 4];
            ar[p] = v;
        }
    };
    auto stsA = [&](uint32_t stg, const float4* ar) {
        #pragma unroll
        for (int p = 0; p < 2; p++) {
            int idx = tid + p * 256;
            int r   = idx >> 3;
            int c4  = idx & 7;
            uint32_t lo0, lo1;
            uint32_t hi0 = split_pair(ar[p].x, ar[p].y, lo0);
            uint32_t hi1 = split_pair(ar[p].z, ar[p].w, lo1);
            uint32_t off = (uint32_t)(r * (G1_LDB * 2) + c4 * 8);
            *(uint2*)(smem + (stg - sb) + OFF_AH + off) = make_uint2(hi0, hi1);
            *(uint2*)(smem + (stg - sb) + OFF_AL + off) = make_uint2(lo0, lo1);
        }
    };
    auto cpB = [&](int k0, uint32_t stg) {
        #pragma unroll
        for (int p = 0; p < 4; p++) {
            int idx = tid + p * 256;
            int pl  = idx >> 9;
            int r   = (idx & 511) >> 2;
            int sg  = idx & 3;
            const __nv_bfloat16* src =
                (pl ? blp : bhp) + (size_t)r * FIN + k0 + sg * 8;
            uint32_t dst = stg + (pl ? OFF_BL : OFF_BH)
                         + (uint32_t)(r * (G1_LDB * 2) + sg * 16);
            CP_ASYNC16(dst, src);
        }
        CP_COMMIT();
    };

    float4 ar[2];
    ldgA(0, ar);
    cpB(0, sb);
    stsA(sb, ar);
    CP_WAIT0();
    __syncthreads();

    const int arow  = (lane & 15);
    const int acol8 = (lane >> 4) * 8;
    const int bg    = lane >> 3;
    const int brow  = ((bg >> 1) * 8) + (lane & 7);
    const int bcol8 = (bg & 1) * 8;

    for (int c = 0; c < G1_NCH; c++) {
        const uint32_t cur = sb + (uint32_t)((c & 1) * G1_STG);
        const uint32_t nxt = sb + (uint32_t)(((c + 1) & 1) * G1_STG);

        if (c + 1 < G1_NCH) {
            ldgA((c + 1) * G1_BK, ar);
            cpB((c + 1) * G1_BK, nxt);
        }

        #pragma unroll
        for (int kk = 0; kk < G1_BK; kk += 16) {
            uint32_t afh[2][4], afl[2][4];
            #pragma unroll
            for (int am = 0; am < 2; am++) {
                uint32_t aoff = (uint32_t)((wm * 32 + am * 16 + arow) * (G1_LDB * 2)
                                           + (kk + acol8) * 2);
                ldsm_x4(afh[am], cur + OFF_AH + aoff);
                ldsm_x4(afl[am], cur + OFF_AL + aoff);
            }
            #pragma unroll
            for (int bp = 0; bp < 2; bp++) {
                uint32_t boff = (uint32_t)((wn * 32 + bp * 16 + brow) * (G1_LDB * 2)
                                           + (kk + bcol8) * 2);
                uint32_t bfh[4], bfl[4];
                ldsm_x4(bfh, cur + OFF_BH + boff);
                ldsm_x4(bfl, cur + OFF_BL + boff);
                #pragma unroll
                for (int am = 0; am < 2; am++) {
                    #pragma unroll
                    for (int j = 0; j < 2; j++) {
                        float* cc = acc[am][bp * 2 + j];
                        mma_bf16(cc, afh[am], bfh + 2 * j);
                        mma_bf16(cc, afh[am], bfl + 2 * j);
                        mma_bf16(cc, afl[am], bfh + 2 * j);
                    }
                }
            }
        }

        if (c + 1 < G1_NCH) {
            stsA(nxt, ar);
            CP_WAIT0();
        }
        __syncthreads();
    }

    const int erow = lane >> 2;
    const int ecol = (lane & 3) * 2;
    #pragma unroll
    for (int am = 0; am < 2; am++) {
        int r0 = m0 + wm * 32 + am * 16 + erow;
        #pragma unroll
        for (int an = 0; an < 4; an++) {
            int colb = wn * 32 + an * 8 + ecol;
            if (r0 < M)
                *(float2*)&g_h1[(size_t)r0 * HDIM + colb] =
                    make_float2(acc[am][an][0], acc[am][an][1]);
            if (r0 + 8 < M)
                *(float2*)&g_h1[(size_t)(r0 + 8) * HDIM + colb] =
                    make_float2(acc[am][an][2], acc[am][an][3]);
        }
    }
}

// ===========================================================================
// CSR aggregation, layer 1
// ===========================================================================
__global__ __launch_bounds__(256)
void agg1_csr_kernel() {
    int warp = (blockIdx.x * blockDim.x + threadIdx.x) >> 5;
    int lane = threadIdx.x & 31;
    if (warp >= NNODES) return;
    int e  = g_offs[warp];
    int nd = g_deg[warp];
    int end = e + nd;

    float4 aA = make_float4(0.f, 0.f, 0.f, 0.f);
    float4 aB = make_float4(0.f, 0.f, 0.f, 0.f);
    const float* __restrict__ h = g_h1;

    for (; e + 1 < end; e += 2) {
        int2 p0 = g_bin[e], p1 = g_bin[e + 1];
        float w0 = __int_as_float(p0.y), w1 = __int_as_float(p1.y);
        float4 v0 = *(const float4*)&h[(size_t)p0.x * HDIM + lane * 4];
        float4 v1 = *(const float4*)&h[(size_t)p1.x * HDIM + lane * 4];
        aA.x = fmaf(w0, v0.x, aA.x); aA.y = fmaf(w0, v0.y, aA.y);
        aA.z = fmaf(w0, v0.z, aA.z); aA.w = fmaf(w0, v0.w, aA.w);
        aB.x = fmaf(w1, v1.x, aB.x); aB.y = fmaf(w1, v1.y, aB.y);
        aB.z = fmaf(w1, v1.z, aB.z); aB.w = fmaf(w1, v1.w, aB.w);
    }
    if (e < end) {
        int2 p0 = g_bin[e];
        float w0 = __int_as_float(p0.y);
        float4 v0 = *(const float4*)&h[(size_t)p0.x * HDIM + lane * 4];
        aA.x = fmaf(w0, v0.x, aA.x); aA.y = fmaf(w0, v0.y, aA.y);
        aA.z = fmaf(w0, v0.z, aA.z); aA.w = fmaf(w0, v0.w, aA.w);
    }
    aA.x += aB.x; aA.y += aB.y; aA.z += aB.z; aA.w += aB.w;
    *(float4*)&g_agg1[(size_t)warp * HDIM + lane * 4] = aA;
}

// ===========================================================================
// GEMM2 via legacy HMMA, 3-split emu, activation fused into the A loader:
//   h2 = act(agg1) @ W2 ; act(v) = relu(v + b1) * (mask >= 0.5 ? 2 : 0)
// CTA: 128(M) x 64(N); 8 warps 4x2; warp tile 32x32; BK=32 double-buffered.
// ===========================================================================
#define G2_BM    128
#define G2_BK    32
#define G2_APL   (G2_BM * G1_LDB * 2)      // 10240 B per A plane
#define G2_BPL   (CDIM * G1_LDB * 2)       // 5120 B per B plane
#define G2_STG   (2 * G2_APL + 2 * G2_BPL) // 30720 B per stage
#define G2_SMEM  (2 * G2_STG)              // 61440 B
#define G2_NCH   (HDIM / G2_BK)            // 4

#define OFF2_AH 0
#define OFF2_AL G2_APL
#define OFF2_BH (2 * G2_APL)
#define OFF2_BL (2 * G2_APL + G2_BPL)

__global__ __launch_bounds__(256)
void gemm2_hmma_kernel(const float* __restrict__ b1, const float* __restrict__ mask,
                       int M) {
    extern __shared__ char smem[];
    const uint32_t sb = smem_u32(smem);
    const int tid  = threadIdx.x;
    const int wid  = tid >> 5;
    const int lane = tid & 31;
    const int wm   = wid >> 1;            // 0..3  (M)
    const int wn   = wid & 1;             // 0..1  (N)
    const int m0   = blockIdx.x * G2_BM;

    const __nv_bfloat16* __restrict__ bhp = g_w2t_hi;
    const __nv_bfloat16* __restrict__ blp = g_w2t_lo;

    float acc[2][4][4];
    #pragma unroll
    for (int i = 0; i < 2; i++)
        #pragma unroll
        for (int j = 0; j < 4; j++)
            #pragma unroll
            for (int q = 0; q < 4; q++) acc[i][j][q] = 0.f;

    // A loader: read agg1 + mask + b1, apply act, keep fp32 in regs
    auto ldgA = [&](int k0, float4* ar) {
        #pragma unroll
        for (int p = 0; p < 4; p++) {
            int idx = tid + p * 256;      // 1024 float4
            int r   = idx >> 3;           // 0..127
            int c4  = idx & 7;
            float4 v = make_float4(0.f, 0.f, 0.f, 0.f);
            if (m0 + r < M) {
                size_t base = (size_t)(m0 + r) * HDIM + k0 + c4 * 4;
                v          = *(const float4*)&g_agg1[base];
                float4 mk  = *(const float4*)&mask[base];
                float4 bb  = *(const float4*)&b1[k0 + c4 * 4];
                v.x = fmaxf(v.x + bb.x, 0.f) * (mk.x >= 0.5f ? 2.f : 0.f);
                v.y = fmaxf(v.y + bb.y, 0.f) * (mk.y >= 0.5f ? 2.f : 0.f);
                v.z = fmaxf(v.z + bb.z, 0.f) * (mk.z >= 0.5f ? 2.f : 0.f);
                v.w = fmaxf(v.w + bb.w, 0.f) * (mk.w >= 0.5f ? 2.f : 0.f);
            }
            ar[p] = v;
        }
    };
    auto stsA = [&](uint32_t stg, const float4* ar) {
        #pragma unroll
        for (int p = 0; p < 4; p++) {
            int idx = tid + p * 256;
            int r   = idx >> 3;
            int c4  = idx & 7;
            uint32_t lo0, lo1;
            uint32_t hi0 = split_pair(ar[p].x, ar[p].y, lo0);
            uint32_t hi1 = split_pair(ar[p].z, ar[p].w, lo1);
            uint32_t off = (uint32_t)(r * (G1_LDB * 2) + c4 * 8);
            *(uint2*)(smem + (stg - sb) + OFF2_AH + off) = make_uint2(hi0, hi1);
            *(uint2*)(smem + (stg - sb) + OFF2_AL + off) = make_uint2(lo0, lo1);
        }
    };
    auto cpB = [&](int k0, uint32_t stg) {
        #pragma unroll
        for (int p = 0; p < 2; p++) {
            int idx = tid + p * 256;      // 512 x 16B (2 planes x 64 rows x 4 segs)
            int pl  = idx >> 8;
            int r   = (idx & 255) >> 2;   // 0..63
            int sg  = idx & 3;
            const __nv_bfloat16* src =
                (pl ? blp : bhp) + (size_t)r * HDIM + k0 + sg * 8;
            uint32_t dst = stg + (pl ? OFF2_BL : OFF2_BH)
                         + (uint32_t)(r * (G1_LDB * 2) + sg * 16);
            CP_ASYNC16(dst, src);
        }
        CP_COMMIT();
    };

    float4 ar[4];
    ldgA(0, ar);
    cpB(0, sb);
    stsA(sb, ar);
    CP_WAIT0();
    __syncthreads();

    const int arow  = (lane & 15);
    const int acol8 = (lane >> 4) * 8;
    const int bg    = lane >> 3;
    const int brow  = ((bg >> 1) * 8) + (lane & 7);
    const int bcol8 = (bg & 1) * 8;

    for (int c = 0; c < G2_NCH; c++) {
        const uint32_t cur = sb + (uint32_t)((c & 1) * G2_STG);
        const uint32_t nxt = sb + (uint32_t)(((c + 1) & 1) * G2_STG);

        if (c + 1 < G2_NCH) {
            ldgA((c + 1) * G2_BK, ar);
            cpB((c + 1) * G2_BK, nxt);
        }

        #pragma unroll
        for (int kk = 0; kk < G2_BK; kk += 16) {
            uint32_t afh[2][4], afl[2][4];
            #pragma unroll
            for (int am = 0; am < 2; am++) {
                uint32_t aoff = (uint32_t)((wm * 32 + am * 16 + arow) * (G1_LDB * 2)
                                           + (kk + acol8) * 2);
                ldsm_x4(afh[am], cur + OFF2_AH + aoff);
                ldsm_x4(afl[am], cur + OFF2_AL + aoff);
            }
            #pragma unroll
            for (int bp = 0; bp < 2; bp++) {
                uint32_t boff = (uint32_t)((wn * 32 + bp * 16 + brow) * (G1_LDB * 2)
                                           + (kk + bcol8) * 2);
                uint32_t bfh[4], bfl[4];
                ldsm_x4(bfh, cur + OFF2_BH + boff);
                ldsm_x4(bfl, cur + OFF2_BL + boff);
                #pragma unroll
                for (int am = 0; am < 2; am++) {
                    #pragma unroll
                    for (int j = 0; j < 2; j++) {
                        float* cc = acc[am][bp * 2 + j];
                        mma_bf16(cc, afh[am], bfh + 2 * j);
                        mma_bf16(cc, afh[am], bfl + 2 * j);
                        mma_bf16(cc, afl[am], bfh + 2 * j);
                    }
                }
            }
        }

        if (c + 1 < G2_NCH) {
            stsA(nxt, ar);
            CP_WAIT0();
        }
        __syncthreads();
    }

    const int erow = lane >> 2;
    const int ecol = (lane & 3) * 2;
    #pragma unroll
    for (int am = 0; am < 2; am++) {
        int r0 = m0 + wm * 32 + am * 16 + erow;
        #pragma unroll
        for (int an = 0; an < 4; an++) {
            int colb = wn * 32 + an * 8 + ecol;
            if (r0 < M)
                *(float2*)&g_h2[(size_t)r0 * CDIM + colb] =
                    make_float2(acc[am][an][0], acc[am][an][1]);
            if (r0 + 8 < M)
                *(float2*)&g_h2[(size_t)(r0 + 8) * CDIM + colb] =
                    make_float2(acc[am][an][2], acc[am][an][3]);
        }
    }
}

// ===========================================================================
// CSR aggregation, layer 2, fused bias + log-softmax
// ===========================================================================
__global__ __launch_bounds__(256)
void agg2_softmax_kernel(const float* __restrict__ b2, float* __restrict__ out) {
    int warp = (blockIdx.x * blockDim.x + threadIdx.x) >> 5;
    int lane = threadIdx.x & 31;
    if (warp >= NNODES) return;
    int e  = g_offs[warp];
    int nd = g_deg[warp];
    int end = e + nd;

    float2 aA = make_float2(0.f, 0.f);
    float2 aB = make_float2(0.f, 0.f);
    const float* __restrict__ h = g_h2;

    for (; e + 1 < end; e += 2) {
        int2 p0 = g_bin[e], p1 = g_bin[e + 1];
        float w0 = __int_as_float(p0.y), w1 = __int_as_float(p1.y);
        float2 v0 = *(const float2*)&h[(size_t)p0.x * CDIM + lane * 2];
        float2 v1 = *(const float2*)&h[(size_t)p1.x * CDIM + lane * 2];
        aA.x = fmaf(w0, v0.x, aA.x); aA.y = fmaf(w0, v0.y, aA.y);
        aB.x = fmaf(w1, v1.x, aB.x); aB.y = fmaf(w1, v1.y, aB.y);
    }
    if (e < end) {
        int2 p0 = g_bin[e];
        float w0 = __int_as_float(p0.y);
        float2 v0 = *(const float2*)&h[(size_t)p0.x * CDIM + lane * 2];
        aA.x = fmaf(w0, v0.x, aA.x); aA.y = fmaf(w0, v0.y, aA.y);
    }
    float2 bb = *(const float2*)&b2[lane * 2];
    float vx = aA.x + aB.x + bb.x;
    float vy = aA.y + aB.y + bb.y;

    float m = fmaxf(vx, vy);
    #pragma unroll
    for (int o = 16; o > 0; o >>= 1) m = fmaxf(m, __shfl_xor_sync(0xFFFFFFFFu, m, o));
    float s = expf(vx - m) + expf(vy - m);
    #pragma unroll
    for (int o = 16; o > 0; o >>= 1) s += __shfl_xor_sync(0xFFFFFFFFu, s, o);
    float lse = m + logf(s);
    *(float2*)&out[(size_t)warp * CDIM + lane * 2] = make_float2(vx - lse, vy - lse);
}

// ===========================================================================
// Launch — CSR build + w2prep forked onto a second stream, under GEMM1.
// ===========================================================================
extern "C" void kernel_launch(void* const* d_in, const int* in_sizes, int n_in,
                              void* d_out, int out_size) {
    const float* x    = (const float*)d_in[0];   // [N, 512]
    const float* ew   = (const float*)d_in[1];   // [E]
    const float* W1   = (const float*)d_in[2];   // [512, 128]
    const float* b1   = (const float*)d_in[3];   // [128]
    const float* W2   = (const float*)d_in[4];   // [128, 64]
    const float* b2   = (const float*)d_in[5];   // [64]
    const float* mask = (const float*)d_in[6];   // [N, 128]
    const int*   ei   = (const int*)d_in[7];     // [2, E]
    float* out = (float*)d_out;

    const int N = NNODES, E = NEDGES;
    const int* src = ei;
    const int* dst = ei + E;

    static cudaStream_t s2 = nullptr;
    static cudaEvent_t  evFork = nullptr, evJoin = nullptr;
    if (!s2) {
        cudaStreamCreateWithFlags(&s2, cudaStreamNonBlocking);
        cudaEventCreateWithFlags(&evFork, cudaEventDisableTiming);
        cudaEventCreateWithFlags(&evJoin, cudaEventDisableTiming);
        cudaFuncSetAttribute(gemm1_hmma_kernel,
                             cudaFuncAttributeMaxDynamicSharedMemorySize, G1_SMEM);
        cudaFuncSetAttribute(gemm2_hmma_kernel,
                             cudaFuncAttributeMaxDynamicSharedMemorySize, G2_SMEM);
    }

    // --- fork: CSR build + W2 prep on s2 (all hidden under gemm1) ---
    cudaEventRecord(evFork, 0);
    cudaStreamWaitEvent(s2, evFork, 0);

    w2prep_kernel<<<(CDIM * HDIM + 255) / 256, 256, 0, s2>>>(W2);
    zero_deg_kernel<<<(N + 255) / 256, 256, 0, s2>>>();
    hist_kernel<<<(E + 255) / 256, 256, 0, s2>>>(dst);
    scan1_kernel<<<NB_SCAN, SCAN_BLK, 0, s2>>>();
    scan2_kernel<<<1, SCAN_BLK, 0, s2>>>();
    scan3_kernel<<<NB_SCAN, SCAN_BLK, 0, s2>>>();
    bin_kernel<<<(E + 255) / 256, 256, 0, s2>>>(src, dst, ew);
    cudaEventRecord(evJoin, s2);

    // --- main stream: W1 split prep, then HMMA GEMM1 ---
    w1prep_kernel<<<(HDIM * FIN + 255) / 256, 256>>>(W1);
    gemm1_hmma_kernel<<<(N + G1_BM - 1) / G1_BM, 256, G1_SMEM>>>(x, N);

    // --- join: aggregation needs both h1 and the CSR bins ---
    cudaStreamWaitEvent(0, evJoin, 0);
    agg1_csr_kernel<<<(N * 32 + 255) / 256, 256>>>();

    // --- layer 2 (HMMA, activation fused in loader) ---
    gemm2_hmma_kernel<<<(N + G2_BM - 1) / G2_BM, 256, G2_SMEM>>>(b1, mask, N);
    agg2_softmax_kernel<<<(N * 32 + 255) / 256, 256>>>(b2, out);
}